// round 8
// baseline (speedup 1.0000x reference)
#include <cuda_runtime.h>
#include <math.h>
#include <stdint.h>

#define N_NODES 50000
#define N_EDGES 800000
#define E_TOT   (N_EDGES + N_NODES)   // 850000 (self loops appended)
#define D 256
#define C_OUT 10
#define NEG_SLOPE 0.2f

// ---------------- device scratch (no allocations allowed) ----------------
__device__ __align__(16) float g_buf0[(size_t)N_NODES * D];   // transformed feats h
__device__ __align__(16) float g_buf1[(size_t)N_NODES * D];   // layer-1 out / layer-2 in
__device__ __align__(16) float g_buf2[(size_t)N_NODES * D];   // layer-2 out / layer-3 in
__device__ __align__(16) float g_h3[(size_t)N_NODES * C_OUT]; // layer-3 transformed feats
__device__ float g_as[N_NODES];
__device__ float g_ad[N_NODES];
__device__ float g_m[N_NODES];
__device__ float g_s[N_NODES];
__device__ float g_p[E_TOT];          // per-edge score -> unnormalized prob
__device__ int   g_src[E_TOT];        // decoded int32 indices (self loops appended)
__device__ int   g_dst[E_TOT];
__device__ int   g_is64;              // 1 if edge_index buffer is int64

// Buffer selector resolved in device code (no host symbol lookups)
__device__ __forceinline__ float* getbuf(int k) {
    return (k == 0) ? g_buf0 : (k == 1) ? g_buf1 : g_buf2;
}

// ---------------- helpers ----------------
__device__ __forceinline__ void atomicMaxF(float* addr, float v) {
    if (v >= 0.f) atomicMax((int*)addr, __float_as_int(v));
    else          atomicMin((unsigned int*)addr, (unsigned int)__float_as_int(v));
}

__device__ __forceinline__ float leaky(float v) {
    return v > 0.f ? v : NEG_SLOPE * v;
}

// ---------------- edge-index dtype detection + decode ----------------
// If the buffer really holds int64 (little-endian, values in [0, 50000)),
// every odd int32 word is 0. For int32 data, odd words are random edge values;
// 32 consecutive zeros has ~0 probability.
__global__ void detect_dtype_kernel(const int* __restrict__ ei32)
{
    int lane = threadIdx.x;                 // 32 threads
    int v = ei32[2 * lane + 1];             // odd words of first 32 entries
    unsigned ballot = __ballot_sync(0xffffffffu, v != 0);
    if (lane == 0) g_is64 = (ballot == 0u) ? 1 : 0;
}

__global__ void decode_edges_kernel(const void* __restrict__ ei_raw)
{
    int e = blockIdx.x * blockDim.x + threadIdx.x;
    if (e >= E_TOT) return;
    int s, d;
    if (e < N_EDGES) {
        if (g_is64) {
            const long long* p = (const long long*)ei_raw;
            s = (int)p[e];
            d = (int)p[N_EDGES + e];
        } else {
            const int* p = (const int*)ei_raw;
            s = p[e];
            d = p[N_EDGES + e];
        }
    } else {
        s = d = e - N_EDGES;               // self loop
    }
    g_src[e] = s;
    g_dst[e] = d;
}

// ---------------- SGEMM: C[M,256] = A[M,256] * B[256,256], fp32 ----------------
// 128x128 tile, BK=8, 256 threads, 8x8 per thread, double-buffered smem.
__global__ __launch_bounds__(256) void sgemm256(const float* __restrict__ Aext,
                                                int asel,
                                                const float* __restrict__ B,
                                                int csel, int M)
{
    const float* A = (asel < 0) ? Aext : getbuf(asel);
    float* C = getbuf(csel);

    __shared__ float As[2][8][128];
    __shared__ float Bs[2][8][128];

    const int tid = threadIdx.x;
    const int blockRow = blockIdx.x * 128;
    const int blockCol = blockIdx.y * 128;

    const int tr = (tid / 16) * 8;
    const int tc = (tid % 16) * 8;

    const int arow = tid >> 1;
    const int acol = (tid & 1) * 4;
    const int brow = tid >> 5;
    const int bcol = (tid & 31) * 4;

    float acc[8][8];
    #pragma unroll
    for (int i = 0; i < 8; i++)
        #pragma unroll
        for (int j = 0; j < 8; j++) acc[i][j] = 0.f;

    const float4 zero4 = make_float4(0.f, 0.f, 0.f, 0.f);
    const int gr = blockRow + arow;

    {
        float4 av = (gr < M) ? *(const float4*)(A + (size_t)gr * 256 + acol) : zero4;
        As[0][acol + 0][arow] = av.x;
        As[0][acol + 1][arow] = av.y;
        As[0][acol + 2][arow] = av.z;
        As[0][acol + 3][arow] = av.w;
        float4 bv = *(const float4*)(B + (size_t)brow * 256 + blockCol + bcol);
        *(float4*)&Bs[0][brow][bcol] = bv;
    }
    __syncthreads();

    int buf = 0;
    for (int k0 = 0; k0 < 256; k0 += 8) {
        if (k0 + 8 < 256) {
            const int nb = buf ^ 1;
            float4 av = (gr < M)
                ? *(const float4*)(A + (size_t)gr * 256 + (k0 + 8) + acol) : zero4;
            As[nb][acol + 0][arow] = av.x;
            As[nb][acol + 1][arow] = av.y;
            As[nb][acol + 2][arow] = av.z;
            As[nb][acol + 3][arow] = av.w;
            float4 bv = *(const float4*)(B + (size_t)(k0 + 8 + brow) * 256 + blockCol + bcol);
            *(float4*)&Bs[nb][brow][bcol] = bv;
        }
        #pragma unroll
        for (int kk = 0; kk < 8; kk++) {
            float ra[8], rb[8];
            #pragma unroll
            for (int i = 0; i < 8; i++) ra[i] = As[buf][kk][tr + i];
            #pragma unroll
            for (int j = 0; j < 8; j++) rb[j] = Bs[buf][kk][tc + j];
            #pragma unroll
            for (int i = 0; i < 8; i++)
                #pragma unroll
                for (int j = 0; j < 8; j++)
                    acc[i][j] = fmaf(ra[i], rb[j], acc[i][j]);
        }
        __syncthreads();
        buf ^= 1;
    }

    #pragma unroll
    for (int i = 0; i < 8; i++) {
        int row = blockRow + tr + i;
        if (row < M) {
            float* cp = C + (size_t)row * 256 + blockCol + tc;
            *(float4*)cp       = make_float4(acc[i][0], acc[i][1], acc[i][2], acc[i][3]);
            *(float4*)(cp + 4) = make_float4(acc[i][4], acc[i][5], acc[i][6], acc[i][7]);
        }
    }
}

// ---------------- alpha: as[i] = h_i . a_src ; ad[i] = h_i . a_dst ----------------
__global__ void alpha_kernel(int hsel,
                             const float* __restrict__ a_src,
                             const float* __restrict__ a_dst)
{
    const float* H = getbuf(hsel);
    int node = blockIdx.x * 8 + (threadIdx.x >> 5);
    int lane = threadIdx.x & 31;
    if (node >= N_NODES) return;
    const float* row = H + (size_t)node * D;
    float s0 = 0.f, s1 = 0.f;
    #pragma unroll
    for (int k = lane; k < D; k += 32) {
        float h = row[k];
        s0 = fmaf(h, a_src[k], s0);
        s1 = fmaf(h, a_dst[k], s1);
    }
    #pragma unroll
    for (int o = 16; o; o >>= 1) {
        s0 += __shfl_xor_sync(0xffffffffu, s0, o);
        s1 += __shfl_xor_sync(0xffffffffu, s1, o);
    }
    if (lane == 0) { g_as[node] = s0; g_ad[node] = s1; }
}

// ---------------- segment softmax scalars ----------------
__global__ void init_seg_kernel()
{
    int i = blockIdx.x * blockDim.x + threadIdx.x;
    if (i < N_NODES) { g_m[i] = -INFINITY; g_s[i] = 0.f; }
}

// pass 1: score e, store it, atomic max per dst
__global__ void edge_max_kernel()
{
    int e = blockIdx.x * blockDim.x + threadIdx.x;
    if (e >= E_TOT) return;
    int s = g_src[e], d = g_dst[e];
    float v = leaky(g_as[s] + g_ad[d]);
    g_p[e] = v;
    atomicMaxF(&g_m[d], v);
}

// pass 2: p = exp(e - m[d]), overwrite g_p, atomic add per dst
__global__ void edge_sum_kernel()
{
    int e = blockIdx.x * blockDim.x + threadIdx.x;
    if (e >= E_TOT) return;
    int d = g_dst[e];
    float p = __expf(g_p[e] - g_m[d]);
    g_p[e] = p;
    atomicAdd(&g_s[d], p);
}

// ---------------- output init: buf[i] = b[i % dout] ----------------
__global__ void init_buf_kernel(int osel, const float* __restrict__ b, int n, int dout)
{
    float* out = getbuf(osel);
    int i = blockIdx.x * blockDim.x + threadIdx.x;
    if (i < n) out[i] = b[i % dout];
}

__global__ void init_out3_kernel(float* __restrict__ out, const float* __restrict__ b, int n)
{
    int i = blockIdx.x * blockDim.x + threadIdx.x;
    if (i < n) out[i] = b[i % C_OUT];
}

// ---------------- aggregation: out[dst] += coeff * h[src], D=256, warp/edge ----------------
__global__ void aggregate_kernel(int hsel, int osel)
{
    const float* H = getbuf(hsel);
    float* out = getbuf(osel);

    int e = blockIdx.x * 8 + (threadIdx.x >> 5);
    int lane = threadIdx.x & 31;
    if (e >= E_TOT) return;
    int s = g_src[e], d = g_dst[e];
    float coeff = g_p[e] / g_s[d];

    const float4* hrow = (const float4*)(H + (size_t)s * D);
    float4* orow = (float4*)(out + (size_t)d * D);
    #pragma unroll
    for (int j = 0; j < 2; j++) {
        int idx = lane + j * 32;                // float4 index 0..63
        float4 hv = hrow[idx];
        hv.x *= coeff; hv.y *= coeff; hv.z *= coeff; hv.w *= coeff;
        atomicAdd(orow + idx, hv);              // vector red (CC >= 9.0)
    }
}

// ---------------- relu in place ----------------
__global__ void relu_kernel(int sel, int n)
{
    float* p = getbuf(sel);
    int i = blockIdx.x * blockDim.x + threadIdx.x;
    if (i < n) p[i] = fmaxf(p[i], 0.f);
}

// ---------------- layer 3: h3 = H @ W3 (256x10) + alpha dots, warp/node ----------------
__global__ void gemm3_alpha_kernel(int hsel,
                                   const float* __restrict__ W3,
                                   const float* __restrict__ a_src,
                                   const float* __restrict__ a_dst)
{
    const float* H = getbuf(hsel);
    __shared__ float Ws[D * C_OUT];
    __shared__ float As3[C_OUT], Ad3[C_OUT];
    int tid = threadIdx.x;
    for (int i = tid; i < D * C_OUT; i += blockDim.x) Ws[i] = W3[i];
    if (tid < C_OUT) { As3[tid] = a_src[tid]; Ad3[tid] = a_dst[tid]; }
    __syncthreads();

    int node = blockIdx.x * 8 + (tid >> 5);
    int lane = tid & 31;
    if (node >= N_NODES) return;
    const float* row = H + (size_t)node * D;
    float acc[C_OUT];
    #pragma unroll
    for (int c = 0; c < C_OUT; c++) acc[c] = 0.f;
    #pragma unroll
    for (int k = lane; k < D; k += 32) {
        float h = row[k];
        #pragma unroll
        for (int c = 0; c < C_OUT; c++) acc[c] = fmaf(h, Ws[k * C_OUT + c], acc[c]);
    }
    #pragma unroll
    for (int c = 0; c < C_OUT; c++)
        #pragma unroll
        for (int o = 16; o; o >>= 1)
            acc[c] += __shfl_xor_sync(0xffffffffu, acc[c], o);
    if (lane == 0) {
        float s0 = 0.f, s1 = 0.f;
        #pragma unroll
        for (int c = 0; c < C_OUT; c++) {
            g_h3[(size_t)node * C_OUT + c] = acc[c];
            s0 = fmaf(acc[c], As3[c], s0);
            s1 = fmaf(acc[c], Ad3[c], s1);
        }
        g_as[node] = s0;
        g_ad[node] = s1;
    }
}

// ---------------- layer 3 aggregation: C=10, thread/edge ----------------
__global__ void aggregate3_kernel(float* __restrict__ out)
{
    int e = blockIdx.x * blockDim.x + threadIdx.x;
    if (e >= E_TOT) return;
    int s = g_src[e], d = g_dst[e];
    float coeff = g_p[e] / g_s[d];
    const float* h = g_h3 + (size_t)s * C_OUT;
    float* o = out + (size_t)d * C_OUT;
    #pragma unroll
    for (int c = 0; c < C_OUT; c++)
        atomicAdd(o + c, h[c] * coeff);
}

// ---------------- host launcher (pure kernel launches; capture-safe) ----------------
extern "C" void kernel_launch(void* const* d_in, const int* in_sizes, int n_in,
                              void* d_out, int out_size)
{
    const float* x     = (const float*)d_in[0];
    const void*  ei    = d_in[1];                 // int32 or int64, detected on device

    const float* W1  = (const float*)d_in[2];
    const float* as1 = (const float*)d_in[3];
    const float* ad1 = (const float*)d_in[4];
    const float* b1  = (const float*)d_in[5];
    const float* W2  = (const float*)d_in[6];
    const float* as2 = (const float*)d_in[7];
    const float* ad2 = (const float*)d_in[8];
    const float* b2  = (const float*)d_in[9];
    const float* W3  = (const float*)d_in[10];
    const float* as3 = (const float*)d_in[11];
    const float* ad3 = (const float*)d_in[12];
    const float* b3  = (const float*)d_in[13];
    float* out = (float*)d_out;

    const dim3 gemmGrid((N_NODES + 127) / 128, 2);
    const int  warpNodeBlocks = (N_NODES + 7) / 8;            // 8 warps/block
    const int  edgeBlocks     = (E_TOT + 255) / 256;
    const int  warpEdgeBlocks = (E_TOT + 7) / 8;
    const int  featN   = N_NODES * D;
    const int  featBlk = (featN + 255) / 256;
    const int  segBlk  = (N_NODES + 255) / 256;

    // ---------------- decode edges once ----------------
    detect_dtype_kernel<<<1, 32>>>((const int*)ei);
    decode_edges_kernel<<<edgeBlocks, 256>>>(ei);

    // ---------------- layer 1:  h -> buf0, agg -> buf1 ----------------
    sgemm256<<<gemmGrid, 256>>>(x, -1, W1, /*csel=*/0, N_NODES);
    alpha_kernel<<<warpNodeBlocks, 256>>>(0, as1, ad1);
    init_seg_kernel<<<segBlk, 256>>>();
    edge_max_kernel<<<edgeBlocks, 256>>>();
    edge_sum_kernel<<<edgeBlocks, 256>>>();
    init_buf_kernel<<<featBlk, 256>>>(1, b1, featN, D);
    aggregate_kernel<<<warpEdgeBlocks, 256>>>(/*hsel=*/0, /*osel=*/1);
    relu_kernel<<<featBlk, 256>>>(1, featN);

    // ---------------- layer 2:  h -> buf0, agg -> buf2 ----------------
    sgemm256<<<gemmGrid, 256>>>(nullptr, 1, W2, /*csel=*/0, N_NODES);
    alpha_kernel<<<warpNodeBlocks, 256>>>(0, as2, ad2);
    init_seg_kernel<<<segBlk, 256>>>();
    edge_max_kernel<<<edgeBlocks, 256>>>();
    edge_sum_kernel<<<edgeBlocks, 256>>>();
    init_buf_kernel<<<featBlk, 256>>>(2, b2, featN, D);
    aggregate_kernel<<<warpEdgeBlocks, 256>>>(/*hsel=*/0, /*osel=*/2);
    relu_kernel<<<featBlk, 256>>>(2, featN);

    // ---------------- layer 3:  h3 from buf2, agg -> d_out ----------------
    gemm3_alpha_kernel<<<warpNodeBlocks, 256>>>(2, W3, as3, ad3);
    init_seg_kernel<<<segBlk, 256>>>();
    edge_max_kernel<<<edgeBlocks, 256>>>();
    edge_sum_kernel<<<edgeBlocks, 256>>>();
    init_out3_kernel<<<(N_NODES * C_OUT + 255) / 256, 256>>>(out, b3, N_NODES * C_OUT);
    aggregate3_kernel<<<edgeBlocks, 256>>>(out);
}

// round 9
// speedup vs baseline: 1.3886x; 1.3886x over previous
#include <cuda_runtime.h>
#include <math.h>
#include <stdint.h>

#define N_NODES 50000
#define N_EDGES 800000
#define E_TOT   (N_EDGES + N_NODES)   // 850000 (self loops appended)
#define D 256
#define C_OUT 10
#define NEG_SLOPE 0.2f
#define CAP 4                          // score slots per lane -> 128 edges/node fast path

// ---------------- device scratch (no allocations allowed) ----------------
__device__ __align__(16) float g_buf0[(size_t)N_NODES * D];   // transformed feats h
__device__ __align__(16) float g_buf1[(size_t)N_NODES * D];   // layer-1 out / layer-2 in
__device__ __align__(16) float g_buf2[(size_t)N_NODES * D];   // layer-2 out / layer-3 in
__device__ __align__(16) float g_h3[(size_t)N_NODES * C_OUT]; // layer-3 transformed feats
__device__ float g_as[N_NODES];
__device__ float g_ad[N_NODES];
__device__ int   g_src[E_TOT];
__device__ int   g_dst[E_TOT];
__device__ int   g_cnt[N_NODES];
__device__ int   g_rowstart[N_NODES + 1];
__device__ int   g_cursor[N_NODES];
__device__ int   g_esrc[E_TOT];       // src ids grouped by dst (CSR)
__device__ int   g_is64;

__device__ __forceinline__ float* getbuf(int k) {
    return (k == 0) ? g_buf0 : (k == 1) ? g_buf1 : g_buf2;
}

__device__ __forceinline__ float leaky(float v) {
    return v > 0.f ? v : NEG_SLOPE * v;
}

// ---------------- edge decode + CSR build ----------------
__global__ void detect_dtype_kernel(const int* __restrict__ ei32)
{
    int lane = threadIdx.x;                 // 32 threads
    int v = ei32[2 * lane + 1];             // odd words: all zero iff int64 data
    unsigned ballot = __ballot_sync(0xffffffffu, v != 0);
    if (lane == 0) g_is64 = (ballot == 0u) ? 1 : 0;
}

__global__ void zero_cnt_kernel()
{
    int i = blockIdx.x * blockDim.x + threadIdx.x;
    if (i < N_NODES) g_cnt[i] = 0;
}

__global__ void decode_hist_kernel(const void* __restrict__ ei_raw)
{
    int e = blockIdx.x * blockDim.x + threadIdx.x;
    if (e >= E_TOT) return;
    int s, d;
    if (e < N_EDGES) {
        if (g_is64) {
            const long long* p = (const long long*)ei_raw;
            s = (int)p[e];
            d = (int)p[N_EDGES + e];
        } else {
            const int* p = (const int*)ei_raw;
            s = p[e];
            d = p[N_EDGES + e];
        }
    } else {
        s = d = e - N_EDGES;               // self loop
    }
    g_src[e] = s;
    g_dst[e] = d;
    atomicAdd(&g_cnt[d], 1);
}

// single block, 1024 threads: exclusive prefix sum of g_cnt -> g_rowstart/g_cursor
__global__ void scan_kernel()
{
    __shared__ int part[1024];
    const int T = 1024;
    int tid = threadIdx.x;
    const int chunk = (N_NODES + T - 1) / T;     // 49
    int base = tid * chunk;
    int sum = 0;
    for (int i = 0; i < chunk; i++) {
        int idx = base + i;
        if (idx < N_NODES) sum += g_cnt[idx];
    }
    part[tid] = sum;
    __syncthreads();
    for (int off = 1; off < T; off <<= 1) {
        int v = (tid >= off) ? part[tid - off] : 0;
        __syncthreads();
        part[tid] += v;
        __syncthreads();
    }
    int run = (tid == 0) ? 0 : part[tid - 1];
    for (int i = 0; i < chunk; i++) {
        int idx = base + i;
        if (idx < N_NODES) {
            g_rowstart[idx] = run;
            g_cursor[idx]   = run;
            run += g_cnt[idx];
        }
    }
    if (tid == 0) g_rowstart[N_NODES] = E_TOT;
}

__global__ void scatter_kernel()
{
    int e = blockIdx.x * blockDim.x + threadIdx.x;
    if (e >= E_TOT) return;
    int d = g_dst[e];
    int pos = atomicAdd(&g_cursor[d], 1);
    g_esrc[pos] = g_src[e];
}

// ---------------- SGEMM: C[M,256] = A[M,256] * B[256,256], fp32 ----------------
// 128x128 tile, BK=8, 256 threads, 8x8/thread, double-buffered. Optional relu on A load.
__global__ __launch_bounds__(256) void sgemm256(const float* __restrict__ Aext,
                                                int asel,
                                                const float* __restrict__ B,
                                                int csel, int M, int reluA)
{
    const float* A = (asel < 0) ? Aext : getbuf(asel);
    float* C = getbuf(csel);

    __shared__ float As[2][8][128];
    __shared__ float Bs[2][8][128];

    const int tid = threadIdx.x;
    const int blockRow = blockIdx.x * 128;
    const int blockCol = blockIdx.y * 128;

    const int tr = (tid / 16) * 8;
    const int tc = (tid % 16) * 8;

    const int arow = tid >> 1;
    const int acol = (tid & 1) * 4;
    const int brow = tid >> 5;
    const int bcol = (tid & 31) * 4;

    float acc[8][8];
    #pragma unroll
    for (int i = 0; i < 8; i++)
        #pragma unroll
        for (int j = 0; j < 8; j++) acc[i][j] = 0.f;

    const float4 zero4 = make_float4(0.f, 0.f, 0.f, 0.f);
    const int gr = blockRow + arow;

    {
        float4 av = (gr < M) ? *(const float4*)(A + (size_t)gr * 256 + acol) : zero4;
        if (reluA) {
            av.x = fmaxf(av.x, 0.f); av.y = fmaxf(av.y, 0.f);
            av.z = fmaxf(av.z, 0.f); av.w = fmaxf(av.w, 0.f);
        }
        As[0][acol + 0][arow] = av.x;
        As[0][acol + 1][arow] = av.y;
        As[0][acol + 2][arow] = av.z;
        As[0][acol + 3][arow] = av.w;
        float4 bv = *(const float4*)(B + (size_t)brow * 256 + blockCol + bcol);
        *(float4*)&Bs[0][brow][bcol] = bv;
    }
    __syncthreads();

    int buf = 0;
    for (int k0 = 0; k0 < 256; k0 += 8) {
        if (k0 + 8 < 256) {
            const int nb = buf ^ 1;
            float4 av = (gr < M)
                ? *(const float4*)(A + (size_t)gr * 256 + (k0 + 8) + acol) : zero4;
            if (reluA) {
                av.x = fmaxf(av.x, 0.f); av.y = fmaxf(av.y, 0.f);
                av.z = fmaxf(av.z, 0.f); av.w = fmaxf(av.w, 0.f);
            }
            As[nb][acol + 0][arow] = av.x;
            As[nb][acol + 1][arow] = av.y;
            As[nb][acol + 2][arow] = av.z;
            As[nb][acol + 3][arow] = av.w;
            float4 bv = *(const float4*)(B + (size_t)(k0 + 8 + brow) * 256 + blockCol + bcol);
            *(float4*)&Bs[nb][brow][bcol] = bv;
        }
        #pragma unroll
        for (int kk = 0; kk < 8; kk++) {
            float ra[8], rb[8];
            #pragma unroll
            for (int i = 0; i < 8; i++) ra[i] = As[buf][kk][tr + i];
            #pragma unroll
            for (int j = 0; j < 8; j++) rb[j] = Bs[buf][kk][tc + j];
            #pragma unroll
            for (int i = 0; i < 8; i++)
                #pragma unroll
                for (int j = 0; j < 8; j++)
                    acc[i][j] = fmaf(ra[i], rb[j], acc[i][j]);
        }
        __syncthreads();
        buf ^= 1;
    }

    #pragma unroll
    for (int i = 0; i < 8; i++) {
        int row = blockRow + tr + i;
        if (row < M) {
            float* cp = C + (size_t)row * 256 + blockCol + tc;
            *(float4*)cp       = make_float4(acc[i][0], acc[i][1], acc[i][2], acc[i][3]);
            *(float4*)(cp + 4) = make_float4(acc[i][4], acc[i][5], acc[i][6], acc[i][7]);
        }
    }
}

// ---------------- alpha: as[i] = h_i . a_src ; ad[i] = h_i . a_dst ----------------
__global__ void alpha_kernel(int hsel,
                             const float* __restrict__ a_src,
                             const float* __restrict__ a_dst)
{
    const float* H = getbuf(hsel);
    int node = blockIdx.x * 8 + (threadIdx.x >> 5);
    int lane = threadIdx.x & 31;
    if (node >= N_NODES) return;
    const float* row = H + (size_t)node * D;
    float s0 = 0.f, s1 = 0.f;
    #pragma unroll
    for (int k = lane; k < D; k += 32) {
        float h = row[k];
        s0 = fmaf(h, a_src[k], s0);
        s1 = fmaf(h, a_dst[k], s1);
    }
    #pragma unroll
    for (int o = 16; o; o >>= 1) {
        s0 += __shfl_xor_sync(0xffffffffu, s0, o);
        s1 += __shfl_xor_sync(0xffffffffu, s1, o);
    }
    if (lane == 0) { g_as[node] = s0; g_ad[node] = s1; }
}

// ---------------- fused softmax + aggregation, warp per dst node (D=256) ----------------
// out[node] = bias + sum_e coeff_e * h[src_e], coeff = softmax over node's in-edges.
__global__ __launch_bounds__(256) void gat_agg_csr(int hsel, int osel,
                                                   const float* __restrict__ bias)
{
    const float* H = getbuf(hsel);
    float* out = getbuf(osel);

    int node = blockIdx.x * 8 + (threadIdx.x >> 5);
    int lane = threadIdx.x & 31;
    if (node >= N_NODES) return;

    const int start = g_rowstart[node];
    const int end   = g_rowstart[node + 1];
    const float adn = g_ad[node];
    const unsigned FULL = 0xffffffffu;

    // ---- pass A: scores (lane-strided), cached in registers ----
    float v[CAP];
    int   sv[CAP];
    float m = -INFINITY;
    int   cnt = 0;
    for (int i = start + lane; i < end; i += 32) {
        int s = g_esrc[i];
        float sc = leaky(g_as[s] + adn);
        if (cnt < CAP) { v[cnt] = sc; sv[cnt] = s; }
        cnt++;
        m = fmaxf(m, sc);
    }
    #pragma unroll
    for (int o = 16; o; o >>= 1) m = fmaxf(m, __shfl_xor_sync(FULL, m, o));

    float psum = 0.f;
    #pragma unroll
    for (int k = 0; k < CAP; k++) {
        if (k < cnt) { v[k] = __expf(v[k] - m); psum += v[k]; }
    }
    // rare overflow tail (deg > 128): recompute
    for (int i = start + lane + CAP * 32; i < end; i += 32) {
        int s = g_esrc[i];
        psum += __expf(leaky(g_as[s] + adn) - m);
    }
    #pragma unroll
    for (int o = 16; o; o >>= 1) psum += __shfl_xor_sync(FULL, psum, o);
    const float inv = 1.f / psum;

    // ---- pass B: weighted gather-accumulate ----
    float4 a0 = make_float4(0.f, 0.f, 0.f, 0.f);
    float4 a1 = make_float4(0.f, 0.f, 0.f, 0.f);
    #pragma unroll
    for (int slot = 0; slot < CAP; slot++) {
        int base = start + slot * 32;
        if (base >= end) break;
        int nown = min(32, end - base);
        float vv = v[slot];
        int   ss = sv[slot];
        for (int owner = 0; owner < nown; owner++) {
            float c = __shfl_sync(FULL, vv, owner) * inv;
            int   s = __shfl_sync(FULL, ss, owner);
            const float4* hr = (const float4*)(H + (size_t)s * D);
            float4 h0 = hr[lane];
            float4 h1 = hr[lane + 32];
            a0.x = fmaf(c, h0.x, a0.x); a0.y = fmaf(c, h0.y, a0.y);
            a0.z = fmaf(c, h0.z, a0.z); a0.w = fmaf(c, h0.w, a0.w);
            a1.x = fmaf(c, h1.x, a1.x); a1.y = fmaf(c, h1.y, a1.y);
            a1.z = fmaf(c, h1.z, a1.z); a1.w = fmaf(c, h1.w, a1.w);
        }
    }
    for (int i = start + CAP * 32; i < end; i++) {      // rare tail
        int s = g_esrc[i];
        float c = __expf(leaky(g_as[s] + adn) - m) * inv;
        const float4* hr = (const float4*)(H + (size_t)s * D);
        float4 h0 = hr[lane];
        float4 h1 = hr[lane + 32];
        a0.x = fmaf(c, h0.x, a0.x); a0.y = fmaf(c, h0.y, a0.y);
        a0.z = fmaf(c, h0.z, a0.z); a0.w = fmaf(c, h0.w, a0.w);
        a1.x = fmaf(c, h1.x, a1.x); a1.y = fmaf(c, h1.y, a1.y);
        a1.z = fmaf(c, h1.z, a1.z); a1.w = fmaf(c, h1.w, a1.w);
    }

    const float4 b0 = ((const float4*)bias)[lane];
    const float4 b1 = ((const float4*)bias)[lane + 32];
    a0.x += b0.x; a0.y += b0.y; a0.z += b0.z; a0.w += b0.w;
    a1.x += b1.x; a1.y += b1.y; a1.z += b1.z; a1.w += b1.w;
    float4* orow = (float4*)(out + (size_t)node * D);
    orow[lane]      = a0;
    orow[lane + 32] = a1;
}

// ---------------- layer 3: h3 = relu(H) @ W3 (256x10) + alpha dots ----------------
__global__ void gemm3_alpha_kernel(int hsel,
                                   const float* __restrict__ W3,
                                   const float* __restrict__ a_src,
                                   const float* __restrict__ a_dst)
{
    const float* H = getbuf(hsel);
    __shared__ float Ws[D * C_OUT];
    __shared__ float As3[C_OUT], Ad3[C_OUT];
    int tid = threadIdx.x;
    for (int i = tid; i < D * C_OUT; i += blockDim.x) Ws[i] = W3[i];
    if (tid < C_OUT) { As3[tid] = a_src[tid]; Ad3[tid] = a_dst[tid]; }
    __syncthreads();

    int node = blockIdx.x * 8 + (tid >> 5);
    int lane = tid & 31;
    if (node >= N_NODES) return;
    const float* row = H + (size_t)node * D;
    float acc[C_OUT];
    #pragma unroll
    for (int c = 0; c < C_OUT; c++) acc[c] = 0.f;
    #pragma unroll
    for (int k = lane; k < D; k += 32) {
        float h = fmaxf(row[k], 0.f);                  // fused relu
        #pragma unroll
        for (int c = 0; c < C_OUT; c++) acc[c] = fmaf(h, Ws[k * C_OUT + c], acc[c]);
    }
    #pragma unroll
    for (int c = 0; c < C_OUT; c++)
        #pragma unroll
        for (int o = 16; o; o >>= 1)
            acc[c] += __shfl_xor_sync(0xffffffffu, acc[c], o);
    if (lane == 0) {
        float s0 = 0.f, s1 = 0.f;
        #pragma unroll
        for (int c = 0; c < C_OUT; c++) {
            g_h3[(size_t)node * C_OUT + c] = acc[c];
            s0 = fmaf(acc[c], As3[c], s0);
            s1 = fmaf(acc[c], Ad3[c], s1);
        }
        g_as[node] = s0;
        g_ad[node] = s1;
    }
}

// ---------------- layer 3 fused softmax + aggregation (C=10), warp per node ----------------
__global__ __launch_bounds__(256) void gat_agg3_csr(float* __restrict__ out,
                                                    const float* __restrict__ b3)
{
    int node = blockIdx.x * 8 + (threadIdx.x >> 5);
    int lane = threadIdx.x & 31;
    if (node >= N_NODES) return;

    const int start = g_rowstart[node];
    const int end   = g_rowstart[node + 1];
    const float adn = g_ad[node];
    const unsigned FULL = 0xffffffffu;

    float v[CAP];
    int   sv[CAP];
    float m = -INFINITY;
    int   cnt = 0;
    for (int i = start + lane; i < end; i += 32) {
        int s = g_esrc[i];
        float sc = leaky(g_as[s] + adn);
        if (cnt < CAP) { v[cnt] = sc; sv[cnt] = s; }
        cnt++;
        m = fmaxf(m, sc);
    }
    #pragma unroll
    for (int o = 16; o; o >>= 1) m = fmaxf(m, __shfl_xor_sync(FULL, m, o));

    float psum = 0.f;
    #pragma unroll
    for (int k = 0; k < CAP; k++) {
        if (k < cnt) { v[k] = __expf(v[k] - m); psum += v[k]; }
    }
    for (int i = start + lane + CAP * 32; i < end; i += 32) {
        int s = g_esrc[i];
        psum += __expf(leaky(g_as[s] + adn) - m);
    }
    #pragma unroll
    for (int o = 16; o; o >>= 1) psum += __shfl_xor_sync(FULL, psum, o);
    const float inv = 1.f / psum;

    float acc = 0.f;
    #pragma unroll
    for (int slot = 0; slot < CAP; slot++) {
        int base = start + slot * 32;
        if (base >= end) break;
        int nown = min(32, end - base);
        float vv = v[slot];
        int   ss = sv[slot];
        for (int owner = 0; owner < nown; owner++) {
            float c = __shfl_sync(FULL, vv, owner) * inv;
            int   s = __shfl_sync(FULL, ss, owner);
            if (lane < C_OUT) acc = fmaf(c, g_h3[(size_t)s * C_OUT + lane], acc);
        }
    }
    for (int i = start + CAP * 32; i < end; i++) {
        int s = g_esrc[i];
        float c = __expf(leaky(g_as[s] + adn) - m) * inv;
        if (lane < C_OUT) acc = fmaf(c, g_h3[(size_t)s * C_OUT + lane], acc);
    }

    if (lane < C_OUT) out[(size_t)node * C_OUT + lane] = acc + b3[lane];
}

// ---------------- host launcher (pure kernel launches; capture-safe) ----------------
extern "C" void kernel_launch(void* const* d_in, const int* in_sizes, int n_in,
                              void* d_out, int out_size)
{
    const float* x  = (const float*)d_in[0];
    const void*  ei = d_in[1];                    // int32 or int64, device-detected

    const float* W1  = (const float*)d_in[2];
    const float* as1 = (const float*)d_in[3];
    const float* ad1 = (const float*)d_in[4];
    const float* b1  = (const float*)d_in[5];
    const float* W2  = (const float*)d_in[6];
    const float* as2 = (const float*)d_in[7];
    const float* ad2 = (const float*)d_in[8];
    const float* b2  = (const float*)d_in[9];
    const float* W3  = (const float*)d_in[10];
    const float* as3 = (const float*)d_in[11];
    const float* ad3 = (const float*)d_in[12];
    const float* b3  = (const float*)d_in[13];
    float* out = (float*)d_out;

    const dim3 gemmGrid((N_NODES + 127) / 128, 2);
    const int  warpNodeBlocks = (N_NODES + 7) / 8;   // 8 warps/block
    const int  edgeBlocks     = (E_TOT + 255) / 256;
    const int  segBlk         = (N_NODES + 255) / 256;

    // ---- CSR build (once per launch) ----
    detect_dtype_kernel<<<1, 32>>>((const int*)ei);
    zero_cnt_kernel<<<segBlk, 256>>>();
    decode_hist_kernel<<<edgeBlocks, 256>>>(ei);
    scan_kernel<<<1, 1024>>>();
    scatter_kernel<<<edgeBlocks, 256>>>();

    // ---- layer 1: h -> buf0, agg -> buf1 ----
    sgemm256<<<gemmGrid, 256>>>(x, -1, W1, /*csel=*/0, N_NODES, /*reluA=*/0);
    alpha_kernel<<<warpNodeBlocks, 256>>>(0, as1, ad1);
    gat_agg_csr<<<warpNodeBlocks, 256>>>(/*hsel=*/0, /*osel=*/1, b1);

    // ---- layer 2: h -> buf0 (relu on A), agg -> buf2 ----
    sgemm256<<<gemmGrid, 256>>>(nullptr, 1, W2, /*csel=*/0, N_NODES, /*reluA=*/1);
    alpha_kernel<<<warpNodeBlocks, 256>>>(0, as2, ad2);
    gat_agg_csr<<<warpNodeBlocks, 256>>>(/*hsel=*/0, /*osel=*/2, b2);

    // ---- layer 3: h3 from relu(buf2), agg -> d_out ----
    gemm3_alpha_kernel<<<warpNodeBlocks, 256>>>(2, W3, as3, ad3);
    gat_agg3_csr<<<warpNodeBlocks, 256>>>(out, b3);
}

// round 10
// speedup vs baseline: 1.6389x; 1.1802x over previous
#include <cuda_runtime.h>
#include <math.h>
#include <stdint.h>

#define N_NODES 50000
#define N_EDGES 800000
#define E_TOT   (N_EDGES + N_NODES)   // 850000 (self loops appended)
#define D 256
#define C_OUT 10
#define NEG_SLOPE 0.2f
#define CAP 4                          // score slots per lane -> 128 edges/node fast path
#define SCAN_B ((N_NODES + 255) / 256) // 196 blocks for hierarchical scan

// ---------------- device scratch (no allocations allowed) ----------------
__device__ __align__(16) float g_buf0[(size_t)N_NODES * D];   // transformed feats h
__device__ __align__(16) float g_buf1[(size_t)N_NODES * D];   // layer-1 out / layer-2 in
__device__ __align__(16) float g_buf2[(size_t)N_NODES * D];   // layer-2 out / layer-3 in
__device__ __align__(16) float g_h3[(size_t)N_NODES * C_OUT]; // layer-3 transformed feats
__device__ float g_as[N_NODES];
__device__ float g_ad[N_NODES];
__device__ int   g_src[E_TOT];
__device__ int   g_dst[E_TOT];
__device__ int   g_cnt[N_NODES];
__device__ int   g_rowstart[N_NODES + 1];
__device__ int   g_cursor[N_NODES];
__device__ int   g_esrc[E_TOT];       // src ids grouped by dst (CSR)
__device__ int   g_bsum[SCAN_B];
__device__ int   g_boff[SCAN_B];
__device__ int   g_is64;

__device__ __forceinline__ float* getbuf(int k) {
    return (k == 0) ? g_buf0 : (k == 1) ? g_buf1 : g_buf2;
}

__device__ __forceinline__ float leaky(float v) {
    return v > 0.f ? v : NEG_SLOPE * v;
}

// packed fp32x2 FMA: d = a*b + d (per 32-bit half). Exact fp32, 2 flops/instr.
__device__ __forceinline__ void ffma2(unsigned long long& d,
                                      unsigned long long a,
                                      unsigned long long b) {
    asm("fma.rn.f32x2 %0, %1, %2, %0;" : "+l"(d) : "l"(a), "l"(b));
}
__device__ __forceinline__ unsigned long long pack2(float lo, float hi) {
    unsigned long long r;
    asm("mov.b64 %0, {%1, %2};" : "=l"(r) : "f"(lo), "f"(hi));
    return r;
}
__device__ __forceinline__ float2 unpack2(unsigned long long v) {
    float2 f;
    asm("mov.b64 {%0, %1}, %2;" : "=f"(f.x), "=f"(f.y) : "l"(v));
    return f;
}

// ---------------- edge decode + CSR build ----------------
__global__ void detect_dtype_kernel(const int* __restrict__ ei32)
{
    int lane = threadIdx.x;                 // 32 threads
    int v = ei32[2 * lane + 1];             // odd words: all zero iff int64 data
    unsigned ballot = __ballot_sync(0xffffffffu, v != 0);
    if (lane == 0) g_is64 = (ballot == 0u) ? 1 : 0;
}

__global__ void zero_cnt_kernel()
{
    int i = blockIdx.x * blockDim.x + threadIdx.x;
    if (i < N_NODES) g_cnt[i] = 0;
}

__global__ void decode_hist_kernel(const void* __restrict__ ei_raw)
{
    int e = blockIdx.x * blockDim.x + threadIdx.x;
    if (e >= E_TOT) return;
    int s, d;
    if (e < N_EDGES) {
        if (g_is64) {
            const long long* p = (const long long*)ei_raw;
            s = (int)p[e];
            d = (int)p[N_EDGES + e];
        } else {
            const int* p = (const int*)ei_raw;
            s = p[e];
            d = p[N_EDGES + e];
        }
    } else {
        s = d = e - N_EDGES;               // self loop
    }
    g_src[e] = s;
    g_dst[e] = d;
    atomicAdd(&g_cnt[d], 1);
}

// ---- hierarchical exclusive scan of g_cnt -> g_rowstart / g_cursor ----
__global__ void scan1_kernel()           // per-block exclusive scan + block sums
{
    __shared__ int sh[256];
    int tid = threadIdx.x;
    int i = blockIdx.x * 256 + tid;
    int v = (i < N_NODES) ? g_cnt[i] : 0;
    sh[tid] = v;
    __syncthreads();
    #pragma unroll
    for (int off = 1; off < 256; off <<= 1) {
        int t = (tid >= off) ? sh[tid - off] : 0;
        __syncthreads();
        sh[tid] += t;
        __syncthreads();
    }
    if (i < N_NODES) g_rowstart[i] = sh[tid] - v;     // exclusive within block
    if (tid == 255) g_bsum[blockIdx.x] = sh[255];
}

__global__ void scan2_kernel()           // 1 block: exclusive scan of 196 block sums
{
    __shared__ int sh[256];
    int tid = threadIdx.x;
    int v = (tid < SCAN_B) ? g_bsum[tid] : 0;
    sh[tid] = v;
    __syncthreads();
    #pragma unroll
    for (int off = 1; off < 256; off <<= 1) {
        int t = (tid >= off) ? sh[tid - off] : 0;
        __syncthreads();
        sh[tid] += t;
        __syncthreads();
    }
    if (tid < SCAN_B) g_boff[tid] = sh[tid] - v;
    if (tid == 0) g_rowstart[N_NODES] = E_TOT;
}

__global__ void scan3_kernel()           // add block offsets, seed cursors
{
    int i = blockIdx.x * blockDim.x + threadIdx.x;
    if (i >= N_NODES) return;
    int r = g_rowstart[i] + g_boff[i >> 8];
    g_rowstart[i] = r;
    g_cursor[i]   = r;
}

__global__ void scatter_kernel()
{
    int e = blockIdx.x * blockDim.x + threadIdx.x;
    if (e >= E_TOT) return;
    int d = g_dst[e];
    int pos = atomicAdd(&g_cursor[d], 1);
    g_esrc[pos] = g_src[e];
}

// ---------------- SGEMM: C[M,256] = A[M,256] * B[256,256], fp32 (FFMA2) ----------------
// 128x128 tile, BK=8, 256 threads, 8x8/thread, double-buffered, packed f32x2 FMA.
__global__ __launch_bounds__(256) void sgemm256(const float* __restrict__ Aext,
                                                int asel,
                                                const float* __restrict__ B,
                                                int csel, int M, int reluA)
{
    const float* A = (asel < 0) ? Aext : getbuf(asel);
    float* C = getbuf(csel);

    __shared__ __align__(16) float As[2][8][128];
    __shared__ __align__(16) float Bs[2][8][128];

    const int tid = threadIdx.x;
    const int blockRow = blockIdx.x * 128;
    const int blockCol = blockIdx.y * 128;

    const int tr = (tid / 16) * 8;
    const int tc = (tid % 16) * 8;

    const int arow = tid >> 1;
    const int acol = (tid & 1) * 4;
    const int brow = tid >> 5;
    const int bcol = (tid & 31) * 4;

    unsigned long long acc2[8][4];       // 8 rows x 4 packed col-pairs
    #pragma unroll
    for (int i = 0; i < 8; i++)
        #pragma unroll
        for (int j = 0; j < 4; j++) acc2[i][j] = 0ull;

    const float4 zero4 = make_float4(0.f, 0.f, 0.f, 0.f);
    const int gr = blockRow + arow;

    {
        float4 av = (gr < M) ? *(const float4*)(A + (size_t)gr * 256 + acol) : zero4;
        if (reluA) {
            av.x = fmaxf(av.x, 0.f); av.y = fmaxf(av.y, 0.f);
            av.z = fmaxf(av.z, 0.f); av.w = fmaxf(av.w, 0.f);
        }
        As[0][acol + 0][arow] = av.x;
        As[0][acol + 1][arow] = av.y;
        As[0][acol + 2][arow] = av.z;
        As[0][acol + 3][arow] = av.w;
        float4 bv = *(const float4*)(B + (size_t)brow * 256 + blockCol + bcol);
        *(float4*)&Bs[0][brow][bcol] = bv;
    }
    __syncthreads();

    int buf = 0;
    for (int k0 = 0; k0 < 256; k0 += 8) {
        if (k0 + 8 < 256) {
            const int nb = buf ^ 1;
            float4 av = (gr < M)
                ? *(const float4*)(A + (size_t)gr * 256 + (k0 + 8) + acol) : zero4;
            if (reluA) {
                av.x = fmaxf(av.x, 0.f); av.y = fmaxf(av.y, 0.f);
                av.z = fmaxf(av.z, 0.f); av.w = fmaxf(av.w, 0.f);
            }
            As[nb][acol + 0][arow] = av.x;
            As[nb][acol + 1][arow] = av.y;
            As[nb][acol + 2][arow] = av.z;
            As[nb][acol + 3][arow] = av.w;
            float4 bv = *(const float4*)(B + (size_t)(k0 + 8 + brow) * 256 + blockCol + bcol);
            *(float4*)&Bs[nb][brow][bcol] = bv;
        }
        #pragma unroll
        for (int kk = 0; kk < 8; kk++) {
            // B row: 8 consecutive floats = 4 packed pairs (LDS.128 x2)
            ulonglong2 rbA = *(const ulonglong2*)&Bs[buf][kk][tc];
            ulonglong2 rbB = *(const ulonglong2*)&Bs[buf][kk][tc + 4];
            unsigned long long rb2[4] = { rbA.x, rbA.y, rbB.x, rbB.y };
            float ra[8];
            #pragma unroll
            for (int i = 0; i < 8; i++) ra[i] = As[buf][kk][tr + i];
            #pragma unroll
            for (int i = 0; i < 8; i++) {
                unsigned long long ra2 = pack2(ra[i], ra[i]);
                #pragma unroll
                for (int j = 0; j < 4; j++)
                    ffma2(acc2[i][j], ra2, rb2[j]);
            }
        }
        __syncthreads();
        buf ^= 1;
    }

    #pragma unroll
    for (int i = 0; i < 8; i++) {
        int row = blockRow + tr + i;
        if (row < M) {
            float2 p0 = unpack2(acc2[i][0]);
            float2 p1 = unpack2(acc2[i][1]);
            float2 p2 = unpack2(acc2[i][2]);
            float2 p3 = unpack2(acc2[i][3]);
            float* cp = C + (size_t)row * 256 + blockCol + tc;
            *(float4*)cp       = make_float4(p0.x, p0.y, p1.x, p1.y);
            *(float4*)(cp + 4) = make_float4(p2.x, p2.y, p3.x, p3.y);
        }
    }
}

// ---------------- alpha: as[i] = h_i . a_src ; ad[i] = h_i . a_dst ----------------
__global__ void alpha_kernel(int hsel,
                             const float* __restrict__ a_src,
                             const float* __restrict__ a_dst)
{
    const float* H = getbuf(hsel);
    int node = blockIdx.x * 8 + (threadIdx.x >> 5);
    int lane = threadIdx.x & 31;
    if (node >= N_NODES) return;
    const float* row = H + (size_t)node * D;
    float s0 = 0.f, s1 = 0.f;
    #pragma unroll
    for (int k = lane; k < D; k += 32) {
        float h = row[k];
        s0 = fmaf(h, a_src[k], s0);
        s1 = fmaf(h, a_dst[k], s1);
    }
    #pragma unroll
    for (int o = 16; o; o >>= 1) {
        s0 += __shfl_xor_sync(0xffffffffu, s0, o);
        s1 += __shfl_xor_sync(0xffffffffu, s1, o);
    }
    if (lane == 0) { g_as[node] = s0; g_ad[node] = s1; }
}

// ---------------- fused softmax + aggregation, warp per dst node (D=256) ----------------
__global__ __launch_bounds__(256) void gat_agg_csr(int hsel, int osel,
                                                   const float* __restrict__ bias)
{
    const float* H = getbuf(hsel);
    float* out = getbuf(osel);

    int node = blockIdx.x * 8 + (threadIdx.x >> 5);
    int lane = threadIdx.x & 31;
    if (node >= N_NODES) return;

    const int start = g_rowstart[node];
    const int end   = g_rowstart[node + 1];
    const float adn = g_ad[node];
    const unsigned FULL = 0xffffffffu;

    float v[CAP];
    int   sv[CAP];
    float m = -INFINITY;
    int   cnt = 0;
    for (int i = start + lane; i < end; i += 32) {
        int s = g_esrc[i];
        float sc = leaky(g_as[s] + adn);
        if (cnt < CAP) { v[cnt] = sc; sv[cnt] = s; }
        cnt++;
        m = fmaxf(m, sc);
    }
    #pragma unroll
    for (int o = 16; o; o >>= 1) m = fmaxf(m, __shfl_xor_sync(FULL, m, o));

    float psum = 0.f;
    #pragma unroll
    for (int k = 0; k < CAP; k++) {
        if (k < cnt) { v[k] = __expf(v[k] - m); psum += v[k]; }
    }
    for (int i = start + lane + CAP * 32; i < end; i += 32) {     // rare tail
        int s = g_esrc[i];
        psum += __expf(leaky(g_as[s] + adn) - m);
    }
    #pragma unroll
    for (int o = 16; o; o >>= 1) psum += __shfl_xor_sync(FULL, psum, o);
    const float inv = 1.f / psum;

    float4 a0 = make_float4(0.f, 0.f, 0.f, 0.f);
    float4 a1 = make_float4(0.f, 0.f, 0.f, 0.f);
    #pragma unroll
    for (int slot = 0; slot < CAP; slot++) {
        int base = start + slot * 32;
        if (base >= end) break;
        int nown = min(32, end - base);
        float vv = v[slot];
        int   ss = sv[slot];
        for (int owner = 0; owner < nown; owner++) {
            float c = __shfl_sync(FULL, vv, owner) * inv;
            int   s = __shfl_sync(FULL, ss, owner);
            const float4* hr = (const float4*)(H + (size_t)s * D);
            float4 h0 = hr[lane];
            float4 h1 = hr[lane + 32];
            a0.x = fmaf(c, h0.x, a0.x); a0.y = fmaf(c, h0.y, a0.y);
            a0.z = fmaf(c, h0.z, a0.z); a0.w = fmaf(c, h0.w, a0.w);
            a1.x = fmaf(c, h1.x, a1.x); a1.y = fmaf(c, h1.y, a1.y);
            a1.z = fmaf(c, h1.z, a1.z); a1.w = fmaf(c, h1.w, a1.w);
        }
    }
    for (int i = start + CAP * 32; i < end; i++) {                // rare tail
        int s = g_esrc[i];
        float c = __expf(leaky(g_as[s] + adn) - m) * inv;
        const float4* hr = (const float4*)(H + (size_t)s * D);
        float4 h0 = hr[lane];
        float4 h1 = hr[lane + 32];
        a0.x = fmaf(c, h0.x, a0.x); a0.y = fmaf(c, h0.y, a0.y);
        a0.z = fmaf(c, h0.z, a0.z); a0.w = fmaf(c, h0.w, a0.w);
        a1.x = fmaf(c, h1.x, a1.x); a1.y = fmaf(c, h1.y, a1.y);
        a1.z = fmaf(c, h1.z, a1.z); a1.w = fmaf(c, h1.w, a1.w);
    }

    const float4 b0 = ((const float4*)bias)[lane];
    const float4 b1 = ((const float4*)bias)[lane + 32];
    a0.x += b0.x; a0.y += b0.y; a0.z += b0.z; a0.w += b0.w;
    a1.x += b1.x; a1.y += b1.y; a1.z += b1.z; a1.w += b1.w;
    float4* orow = (float4*)(out + (size_t)node * D);
    orow[lane]      = a0;
    orow[lane + 32] = a1;
}

// ---------------- layer 3: h3 = relu(H) @ W3 (256x10) + alpha dots ----------------
__global__ void gemm3_alpha_kernel(int hsel,
                                   const float* __restrict__ W3,
                                   const float* __restrict__ a_src,
                                   const float* __restrict__ a_dst)
{
    const float* H = getbuf(hsel);
    __shared__ float Ws[D * C_OUT];
    __shared__ float As3[C_OUT], Ad3[C_OUT];
    int tid = threadIdx.x;
    for (int i = tid; i < D * C_OUT; i += blockDim.x) Ws[i] = W3[i];
    if (tid < C_OUT) { As3[tid] = a_src[tid]; Ad3[tid] = a_dst[tid]; }
    __syncthreads();

    int node = blockIdx.x * 8 + (tid >> 5);
    int lane = tid & 31;
    if (node >= N_NODES) return;
    const float* row = H + (size_t)node * D;
    float acc[C_OUT];
    #pragma unroll
    for (int c = 0; c < C_OUT; c++) acc[c] = 0.f;
    #pragma unroll
    for (int k = lane; k < D; k += 32) {
        float h = fmaxf(row[k], 0.f);                  // fused relu
        #pragma unroll
        for (int c = 0; c < C_OUT; c++) acc[c] = fmaf(h, Ws[k * C_OUT + c], acc[c]);
    }
    #pragma unroll
    for (int c = 0; c < C_OUT; c++)
        #pragma unroll
        for (int o = 16; o; o >>= 1)
            acc[c] += __shfl_xor_sync(0xffffffffu, acc[c], o);
    if (lane == 0) {
        float s0 = 0.f, s1 = 0.f;
        #pragma unroll
        for (int c = 0; c < C_OUT; c++) {
            g_h3[(size_t)node * C_OUT + c] = acc[c];
            s0 = fmaf(acc[c], As3[c], s0);
            s1 = fmaf(acc[c], Ad3[c], s1);
        }
        g_as[node] = s0;
        g_ad[node] = s1;
    }
}

// ---------------- layer 3 fused softmax + aggregation (C=10), warp per node ----------------
__global__ __launch_bounds__(256) void gat_agg3_csr(float* __restrict__ out,
                                                    const float* __restrict__ b3)
{
    int node = blockIdx.x * 8 + (threadIdx.x >> 5);
    int lane = threadIdx.x & 31;
    if (node >= N_NODES) return;

    const int start = g_rowstart[node];
    const int end   = g_rowstart[node + 1];
    const float adn = g_ad[node];
    const unsigned FULL = 0xffffffffu;

    float v[CAP];
    int   sv[CAP];
    float m = -INFINITY;
    int   cnt = 0;
    for (int i = start + lane; i < end; i += 32) {
        int s = g_esrc[i];
        float sc = leaky(g_as[s] + adn);
        if (cnt < CAP) { v[cnt] = sc; sv[cnt] = s; }
        cnt++;
        m = fmaxf(m, sc);
    }
    #pragma unroll
    for (int o = 16; o; o >>= 1) m = fmaxf(m, __shfl_xor_sync(FULL, m, o));

    float psum = 0.f;
    #pragma unroll
    for (int k = 0; k < CAP; k++) {
        if (k < cnt) { v[k] = __expf(v[k] - m); psum += v[k]; }
    }
    for (int i = start + lane + CAP * 32; i < end; i += 32) {
        int s = g_esrc[i];
        psum += __expf(leaky(g_as[s] + adn) - m);
    }
    #pragma unroll
    for (int o = 16; o; o >>= 1) psum += __shfl_xor_sync(FULL, psum, o);
    const float inv = 1.f / psum;

    float acc = 0.f;
    #pragma unroll
    for (int slot = 0; slot < CAP; slot++) {
        int base = start + slot * 32;
        if (base >= end) break;
        int nown = min(32, end - base);
        float vv = v[slot];
        int   ss = sv[slot];
        for (int owner = 0; owner < nown; owner++) {
            float c = __shfl_sync(FULL, vv, owner) * inv;
            int   s = __shfl_sync(FULL, ss, owner);
            if (lane < C_OUT) acc = fmaf(c, g_h3[(size_t)s * C_OUT + lane], acc);
        }
    }
    for (int i = start + CAP * 32; i < end; i++) {
        int s = g_esrc[i];
        float c = __expf(leaky(g_as[s] + adn) - m) * inv;
        if (lane < C_OUT) acc = fmaf(c, g_h3[(size_t)s * C_OUT + lane], acc);
    }

    if (lane < C_OUT) out[(size_t)node * C_OUT + lane] = acc + b3[lane];
}

// ---------------- host launcher (pure kernel launches; capture-safe) ----------------
extern "C" void kernel_launch(void* const* d_in, const int* in_sizes, int n_in,
                              void* d_out, int out_size)
{
    const float* x  = (const float*)d_in[0];
    const void*  ei = d_in[1];                    // int32 or int64, device-detected

    const float* W1  = (const float*)d_in[2];
    const float* as1 = (const float*)d_in[3];
    const float* ad1 = (const float*)d_in[4];
    const float* b1  = (const float*)d_in[5];
    const float* W2  = (const float*)d_in[6];
    const float* as2 = (const float*)d_in[7];
    const float* ad2 = (const float*)d_in[8];
    const float* b2  = (const float*)d_in[9];
    const float* W3  = (const float*)d_in[10];
    const float* as3 = (const float*)d_in[11];
    const float* ad3 = (const float*)d_in[12];
    const float* b3  = (const float*)d_in[13];
    float* out = (float*)d_out;

    const dim3 gemmGrid((N_NODES + 127) / 128, 2);
    const int  warpNodeBlocks = (N_NODES + 7) / 8;   // 8 warps/block
    const int  edgeBlocks     = (E_TOT + 255) / 256;
    const int  segBlk         = (N_NODES + 255) / 256;

    // ---- CSR build (once per launch) ----
    detect_dtype_kernel<<<1, 32>>>((const int*)ei);
    zero_cnt_kernel<<<segBlk, 256>>>();
    decode_hist_kernel<<<edgeBlocks, 256>>>(ei);
    scan1_kernel<<<SCAN_B, 256>>>();
    scan2_kernel<<<1, 256>>>();
    scan3_kernel<<<segBlk, 256>>>();
    scatter_kernel<<<edgeBlocks, 256>>>();

    // ---- layer 1: h -> buf0, agg -> buf1 ----
    sgemm256<<<gemmGrid, 256>>>(x, -1, W1, /*csel=*/0, N_NODES, /*reluA=*/0);
    alpha_kernel<<<warpNodeBlocks, 256>>>(0, as1, ad1);
    gat_agg_csr<<<warpNodeBlocks, 256>>>(/*hsel=*/0, /*osel=*/1, b1);

    // ---- layer 2: h -> buf0 (relu on A), agg -> buf2 ----
    sgemm256<<<gemmGrid, 256>>>(nullptr, 1, W2, /*csel=*/0, N_NODES, /*reluA=*/1);
    alpha_kernel<<<warpNodeBlocks, 256>>>(0, as2, ad2);
    gat_agg_csr<<<warpNodeBlocks, 256>>>(/*hsel=*/0, /*osel=*/2, b2);

    // ---- layer 3: h3 from relu(buf2), agg -> d_out ----
    gemm3_alpha_kernel<<<warpNodeBlocks, 256>>>(2, W3, as3, ad3);
    gat_agg3_csr<<<warpNodeBlocks, 256>>>(out, b3);
}

// round 14
// speedup vs baseline: 1.7737x; 1.0822x over previous
#include <cuda_runtime.h>
#include <math.h>
#include <stdint.h>

#define N_NODES 50000
#define N_EDGES 800000
#define E_TOT   (N_EDGES + N_NODES)   // 850000 (self loops appended)
#define D 256
#define C_OUT 10
#define NEG_SLOPE 0.2f
#define CAP 4                          // score slots per lane -> 128 edges/node fast path
#define SCAN_B ((N_NODES + 255) / 256) // 196 blocks for hierarchical scan

// ---------------- device scratch (no allocations allowed) ----------------
__device__ __align__(16) float g_buf0[(size_t)N_NODES * D];   // transformed feats h
__device__ __align__(16) float g_buf1[(size_t)N_NODES * D];   // layer-1 out / layer-2 in
__device__ __align__(16) float g_buf2[(size_t)N_NODES * D];   // layer-2 out / layer-3 in
__device__ __align__(16) float g_h3[(size_t)N_NODES * C_OUT]; // layer-3 transformed feats
__device__ float g_as[N_NODES];
__device__ float g_ad[N_NODES];
__device__ int   g_src[E_TOT];
__device__ int   g_dst[E_TOT];
__device__ int   g_cnt[N_NODES];
__device__ int   g_rowstart[N_NODES + 1];
__device__ int   g_cursor[N_NODES];
__device__ int   g_esrc[E_TOT];       // src ids grouped by dst (CSR)
__device__ int   g_bsum[SCAN_B];
__device__ int   g_boff[SCAN_B];
__device__ int   g_is64;

__device__ __forceinline__ float* getbuf(int k) {
    return (k == 0) ? g_buf0 : (k == 1) ? g_buf1 : g_buf2;
}

__device__ __forceinline__ float leaky(float v) {
    return v > 0.f ? v : NEG_SLOPE * v;
}

// ---------------- tf32 helpers ----------------
__device__ __forceinline__ unsigned f2tf32(float x) {
    unsigned r;
    asm("cvt.rna.tf32.f32 %0, %1;" : "=r"(r) : "f"(x));
    return r;
}

// m16n8k8 tf32 mma, row.col, fp32 accumulate (in place)
__device__ __forceinline__ void mma_tf32(float* c, const unsigned* a, const unsigned* b) {
    asm volatile(
        "mma.sync.aligned.m16n8k8.row.col.f32.tf32.tf32.f32 "
        "{%0,%1,%2,%3}, {%4,%5,%6,%7}, {%8,%9}, {%0,%1,%2,%3};"
        : "+f"(c[0]), "+f"(c[1]), "+f"(c[2]), "+f"(c[3])
        : "r"(a[0]), "r"(a[1]), "r"(a[2]), "r"(a[3]), "r"(b[0]), "r"(b[1]));
}

// ---------------- edge decode + CSR build ----------------
__global__ void detect_dtype_kernel(const int* __restrict__ ei32)
{
    int lane = threadIdx.x;                 // 32 threads
    int v = ei32[2 * lane + 1];             // odd words: all zero iff int64 data
    unsigned ballot = __ballot_sync(0xffffffffu, v != 0);
    if (lane == 0) g_is64 = (ballot == 0u) ? 1 : 0;
}

__global__ void zero_cnt_kernel()
{
    int i = blockIdx.x * blockDim.x + threadIdx.x;
    if (i < N_NODES) g_cnt[i] = 0;
}

__global__ void decode_hist_kernel(const void* __restrict__ ei_raw)
{
    int e = blockIdx.x * blockDim.x + threadIdx.x;
    if (e >= E_TOT) return;
    int s, d;
    if (e < N_EDGES) {
        if (g_is64) {
            const long long* p = (const long long*)ei_raw;
            s = (int)p[e];
            d = (int)p[N_EDGES + e];
        } else {
            const int* p = (const int*)ei_raw;
            s = p[e];
            d = p[N_EDGES + e];
        }
    } else {
        s = d = e - N_EDGES;               // self loop
    }
    g_src[e] = s;
    g_dst[e] = d;
    atomicAdd(&g_cnt[d], 1);
}

// ---- hierarchical exclusive scan of g_cnt -> g_rowstart / g_cursor ----
__global__ void scan1_kernel()           // per-block exclusive scan + block sums
{
    __shared__ int sh[256];
    int tid = threadIdx.x;
    int i = blockIdx.x * 256 + tid;
    int v = (i < N_NODES) ? g_cnt[i] : 0;
    sh[tid] = v;
    __syncthreads();
    #pragma unroll
    for (int off = 1; off < 256; off <<= 1) {
        int t = (tid >= off) ? sh[tid - off] : 0;
        __syncthreads();
        sh[tid] += t;
        __syncthreads();
    }
    if (i < N_NODES) g_rowstart[i] = sh[tid] - v;     // exclusive within block
    if (tid == 255) g_bsum[blockIdx.x] = sh[255];
}

__global__ void scan2_kernel()           // 1 block: exclusive scan of 196 block sums
{
    __shared__ int sh[256];
    int tid = threadIdx.x;
    int v = (tid < SCAN_B) ? g_bsum[tid] : 0;
    sh[tid] = v;
    __syncthreads();
    #pragma unroll
    for (int off = 1; off < 256; off <<= 1) {
        int t = (tid >= off) ? sh[tid - off] : 0;
        __syncthreads();
        sh[tid] += t;
        __syncthreads();
    }
    if (tid < SCAN_B) g_boff[tid] = sh[tid] - v;
    if (tid == 0) g_rowstart[N_NODES] = E_TOT;
}

__global__ void scan3_kernel()           // add block offsets, seed cursors
{
    int i = blockIdx.x * blockDim.x + threadIdx.x;
    if (i >= N_NODES) return;
    int r = g_rowstart[i] + g_boff[i >> 8];
    g_rowstart[i] = r;
    g_cursor[i]   = r;
}

__global__ void scatter_kernel()
{
    int e = blockIdx.x * blockDim.x + threadIdx.x;
    if (e >= E_TOT) return;
    int d = g_dst[e];
    int pos = atomicAdd(&g_cursor[d], 1);
    g_esrc[pos] = g_src[e];
}

// ---------------- TF32 tensor-core SGEMM: C[M,256] = A[M,256]*B[256,256] ------
// 128x128 block, BK=16, 8 warps (4 row x 2 col), warp tile 32x64.
// 3xTF32 split (hi*hi + hi*lo + lo*hi) -> ~fp32 accuracy.
#define GA_S 20     // A smem row stride (u32), 20r mod 32 distinct over r -> conflict-free
#define GB_S 132    // B smem k-row stride (u32)

__global__ __launch_bounds__(256) void sgemm256(const float* __restrict__ Aext,
                                                int asel,
                                                const float* __restrict__ B,
                                                int csel, int M, int reluA)
{
    const float* A = (asel < 0) ? Aext : getbuf(asel);
    float* C = getbuf(csel);

    __shared__ unsigned Ahi[128 * GA_S];
    __shared__ unsigned Alo[128 * GA_S];
    __shared__ unsigned Bhi[16 * GB_S];
    __shared__ unsigned Blo[16 * GB_S];

    const int tid = threadIdx.x;
    const int lane = tid & 31;
    const int wid  = tid >> 5;
    const int wr = wid & 3;            // warp row 0..3 -> m offset 32*wr
    const int wc = wid >> 2;           // warp col 0..1 -> n offset 64*wc
    const int g  = lane >> 2;          // group id 0..7
    const int q  = lane & 3;           // thread in group 0..3

    const int blockRow = blockIdx.x * 128;
    const int blockCol = blockIdx.y * 128;

    // global load assignments
    const int arow_l = tid >> 2;       // 0..63 (+64 on 2nd iter)
    const int ac4    = tid & 3;        // col4 within 16-wide K panel
    const int brow_l = tid >> 5;       // 0..7  (+8 on 2nd iter)
    const int bc4    = tid & 31;       // col4 within 128-wide N panel

    float acc[2][8][4];
    #pragma unroll
    for (int mt = 0; mt < 2; mt++)
        #pragma unroll
        for (int nt = 0; nt < 8; nt++)
            #pragma unroll
            for (int r = 0; r < 4; r++) acc[mt][nt][r] = 0.f;

    const float4 zero4 = make_float4(0.f, 0.f, 0.f, 0.f);
    float4 pa[2], pb[2];

    // prologue: load tile 0 into regs
    #pragma unroll
    for (int i = 0; i < 2; i++) {
        int ar = arow_l + 64 * i;
        int grow = blockRow + ar;
        pa[i] = (grow < M) ? *(const float4*)(A + (size_t)grow * 256 + ac4 * 4) : zero4;
        int br = brow_l + 8 * i;
        pb[i] = *(const float4*)(B + (size_t)br * 256 + blockCol + bc4 * 4);
    }

    for (int kb = 0; kb < 16; kb++) {
        // split + store current tile to smem
        #pragma unroll
        for (int i = 0; i < 2; i++) {
            float vv[4] = { pa[i].x, pa[i].y, pa[i].z, pa[i].w };
            if (reluA) {
                #pragma unroll
                for (int j = 0; j < 4; j++) vv[j] = fmaxf(vv[j], 0.f);
            }
            unsigned hi[4], lo[4];
            #pragma unroll
            for (int j = 0; j < 4; j++) {
                hi[j] = f2tf32(vv[j]);
                lo[j] = f2tf32(vv[j] - __uint_as_float(hi[j]));
            }
            int idx = (arow_l + 64 * i) * GA_S + ac4 * 4;
            *(uint2*)&Ahi[idx]     = make_uint2(hi[0], hi[1]);
            *(uint2*)&Ahi[idx + 2] = make_uint2(hi[2], hi[3]);
            *(uint2*)&Alo[idx]     = make_uint2(lo[0], lo[1]);
            *(uint2*)&Alo[idx + 2] = make_uint2(lo[2], lo[3]);

            float wv[4] = { pb[i].x, pb[i].y, pb[i].z, pb[i].w };
            unsigned bh[4], bl[4];
            #pragma unroll
            for (int j = 0; j < 4; j++) {
                bh[j] = f2tf32(wv[j]);
                bl[j] = f2tf32(wv[j] - __uint_as_float(bh[j]));
            }
            int bidx = (brow_l + 8 * i) * GB_S + bc4 * 4;
            *(uint2*)&Bhi[bidx]     = make_uint2(bh[0], bh[1]);
            *(uint2*)&Bhi[bidx + 2] = make_uint2(bh[2], bh[3]);
            *(uint2*)&Blo[bidx]     = make_uint2(bl[0], bl[1]);
            *(uint2*)&Blo[bidx + 2] = make_uint2(bl[2], bl[3]);
        }
        __syncthreads();

        // prefetch next tile
        if (kb < 15) {
            #pragma unroll
            for (int i = 0; i < 2; i++) {
                int ar = arow_l + 64 * i;
                int grow = blockRow + ar;
                pa[i] = (grow < M)
                    ? *(const float4*)(A + (size_t)grow * 256 + (kb + 1) * 16 + ac4 * 4)
                    : zero4;
                int br = brow_l + 8 * i;
                pb[i] = *(const float4*)(B + (size_t)((kb + 1) * 16 + br) * 256
                                         + blockCol + bc4 * 4);
            }
        }

        // compute: 2 k-steps of k8
        #pragma unroll
        for (int ks = 0; ks < 2; ks++) {
            const int k0 = ks * 8;
            unsigned ah[2][4], al[2][4];
            #pragma unroll
            for (int mt = 0; mt < 2; mt++) {
                int r0 = (wr * 32 + mt * 16 + g) * GA_S;
                int r1 = r0 + 8 * GA_S;
                ah[mt][0] = Ahi[r0 + k0 + q];     al[mt][0] = Alo[r0 + k0 + q];
                ah[mt][1] = Ahi[r1 + k0 + q];     al[mt][1] = Alo[r1 + k0 + q];
                ah[mt][2] = Ahi[r0 + k0 + q + 4]; al[mt][2] = Alo[r0 + k0 + q + 4];
                ah[mt][3] = Ahi[r1 + k0 + q + 4]; al[mt][3] = Alo[r1 + k0 + q + 4];
            }
            unsigned bh[8][2], bl[8][2];
            #pragma unroll
            for (int nt = 0; nt < 8; nt++) {
                int n = wc * 64 + nt * 8 + g;
                bh[nt][0] = Bhi[(k0 + q) * GB_S + n];
                bh[nt][1] = Bhi[(k0 + q + 4) * GB_S + n];
                bl[nt][0] = Blo[(k0 + q) * GB_S + n];
                bl[nt][1] = Blo[(k0 + q + 4) * GB_S + n];
            }
            #pragma unroll
            for (int mt = 0; mt < 2; mt++)
                #pragma unroll
                for (int nt = 0; nt < 8; nt++) {
                    mma_tf32(acc[mt][nt], al[mt], bh[nt]);   // lo*hi
                    mma_tf32(acc[mt][nt], ah[mt], bl[nt]);   // hi*lo
                    mma_tf32(acc[mt][nt], ah[mt], bh[nt]);   // hi*hi
                }
        }
        __syncthreads();
    }

    // epilogue
    #pragma unroll
    for (int mt = 0; mt < 2; mt++) {
        int row0 = blockRow + wr * 32 + mt * 16 + g;
        int row1 = row0 + 8;
        #pragma unroll
        for (int nt = 0; nt < 8; nt++) {
            int col = blockCol + wc * 64 + nt * 8 + q * 2;
            if (row0 < M)
                *(float2*)(C + (size_t)row0 * 256 + col) =
                    make_float2(acc[mt][nt][0], acc[mt][nt][1]);
            if (row1 < M)
                *(float2*)(C + (size_t)row1 * 256 + col) =
                    make_float2(acc[mt][nt][2], acc[mt][nt][3]);
        }
    }
}

// ---------------- alpha: as[i] = h_i . a_src ; ad[i] = h_i . a_dst ----------------
__global__ void alpha_kernel(int hsel,
                             const float* __restrict__ a_src,
                             const float* __restrict__ a_dst)
{
    const float* H = getbuf(hsel);
    int node = blockIdx.x * 8 + (threadIdx.x >> 5);
    int lane = threadIdx.x & 31;
    if (node >= N_NODES) return;
    const float* row = H + (size_t)node * D;
    float s0 = 0.f, s1 = 0.f;
    #pragma unroll
    for (int k = lane; k < D; k += 32) {
        float h = row[k];
        s0 = fmaf(h, a_src[k], s0);
        s1 = fmaf(h, a_dst[k], s1);
    }
    #pragma unroll
    for (int o = 16; o; o >>= 1) {
        s0 += __shfl_xor_sync(0xffffffffu, s0, o);
        s1 += __shfl_xor_sync(0xffffffffu, s1, o);
    }
    if (lane == 0) { g_as[node] = s0; g_ad[node] = s1; }
}

// ---------------- fused softmax + aggregation, warp per dst node (D=256) ----------------
__global__ __launch_bounds__(256) void gat_agg_csr(int hsel, int osel,
                                                   const float* __restrict__ bias)
{
    const float* H = getbuf(hsel);
    float* out = getbuf(osel);

    int node = blockIdx.x * 8 + (threadIdx.x >> 5);
    int lane = threadIdx.x & 31;
    if (node >= N_NODES) return;

    const int start = g_rowstart[node];
    const int end   = g_rowstart[node + 1];
    const float adn = g_ad[node];
    const unsigned FULL = 0xffffffffu;

    float v[CAP];
    int   sv[CAP];
    float m = -INFINITY;
    int   cnt = 0;
    for (int i = start + lane; i < end; i += 32) {
        int s = g_esrc[i];
        float sc = leaky(g_as[s] + adn);
        if (cnt < CAP) { v[cnt] = sc; sv[cnt] = s; }
        cnt++;
        m = fmaxf(m, sc);
    }
    #pragma unroll
    for (int o = 16; o; o >>= 1) m = fmaxf(m, __shfl_xor_sync(FULL, m, o));

    float psum = 0.f;
    #pragma unroll
    for (int k = 0; k < CAP; k++) {
        if (k < cnt) { v[k] = __expf(v[k] - m); psum += v[k]; }
    }
    for (int i = start + lane + CAP * 32; i < end; i += 32) {     // rare tail
        int s = g_esrc[i];
        psum += __expf(leaky(g_as[s] + adn) - m);
    }
    #pragma unroll
    for (int o = 16; o; o >>= 1) psum += __shfl_xor_sync(FULL, psum, o);
    const float inv = 1.f / psum;

    float4 a0 = make_float4(0.f, 0.f, 0.f, 0.f);
    float4 a1 = make_float4(0.f, 0.f, 0.f, 0.f);
    #pragma unroll
    for (int slot = 0; slot < CAP; slot++) {
        int base = start + slot * 32;
        if (base >= end) break;
        int nown = min(32, end - base);
        float vv = v[slot];
        int   ss = sv[slot];
        for (int owner = 0; owner < nown; owner++) {
            float c = __shfl_sync(FULL, vv, owner) * inv;
            int   s = __shfl_sync(FULL, ss, owner);
            const float4* hr = (const float4*)(H + (size_t)s * D);
            float4 h0 = hr[lane];
            float4 h1 = hr[lane + 32];
            a0.x = fmaf(c, h0.x, a0.x); a0.y = fmaf(c, h0.y, a0.y);
            a0.z = fmaf(c, h0.z, a0.z); a0.w = fmaf(c, h0.w, a0.w);
            a1.x = fmaf(c, h1.x, a1.x); a1.y = fmaf(c, h1.y, a1.y);
            a1.z = fmaf(c, h1.z, a1.z); a1.w = fmaf(c, h1.w, a1.w);
        }
    }
    for (int i = start + CAP * 32; i < end; i++) {                // rare tail
        int s = g_esrc[i];
        float c = __expf(leaky(g_as[s] + adn) - m) * inv;
        const float4* hr = (const float4*)(H + (size_t)s * D);
        float4 h0 = hr[lane];
        float4 h1 = hr[lane + 32];
        a0.x = fmaf(c, h0.x, a0.x); a0.y = fmaf(c, h0.y, a0.y);
        a0.z = fmaf(c, h0.z, a0.z); a0.w = fmaf(c, h0.w, a0.w);
        a1.x = fmaf(c, h1.x, a1.x); a1.y = fmaf(c, h1.y, a1.y);
        a1.z = fmaf(c, h1.z, a1.z); a1.w = fmaf(c, h1.w, a1.w);
    }

    const float4 b0 = ((const float4*)bias)[lane];
    const float4 b1 = ((const float4*)bias)[lane + 32];
    a0.x += b0.x; a0.y += b0.y; a0.z += b0.z; a0.w += b0.w;
    a1.x += b1.x; a1.y += b1.y; a1.z += b1.z; a1.w += b1.w;
    float4* orow = (float4*)(out + (size_t)node * D);
    orow[lane]      = a0;
    orow[lane + 32] = a1;
}

// ---------------- layer 3: h3 = relu(H) @ W3 (256x10) + alpha dots ----------------
__global__ void gemm3_alpha_kernel(int hsel,
                                   const float* __restrict__ W3,
                                   const float* __restrict__ a_src,
                                   const float* __restrict__ a_dst)
{
    const float* H = getbuf(hsel);
    __shared__ float Ws[D * C_OUT];
    __shared__ float As3[C_OUT], Ad3[C_OUT];
    int tid = threadIdx.x;
    for (int i = tid; i < D * C_OUT; i += blockDim.x) Ws[i] = W3[i];
    if (tid < C_OUT) { As3[tid] = a_src[tid]; Ad3[tid] = a_dst[tid]; }
    __syncthreads();

    int node = blockIdx.x * 8 + (tid >> 5);
    int lane = tid & 31;
    if (node >= N_NODES) return;
    const float* row = H + (size_t)node * D;
    float acc[C_OUT];
    #pragma unroll
    for (int c = 0; c < C_OUT; c++) acc[c] = 0.f;
    #pragma unroll
    for (int k = lane; k < D; k += 32) {
        float h = fmaxf(row[k], 0.f);                  // fused relu
        #pragma unroll
        for (int c = 0; c < C_OUT; c++) acc[c] = fmaf(h, Ws[k * C_OUT + c], acc[c]);
    }
    #pragma unroll
    for (int c = 0; c < C_OUT; c++)
        #pragma unroll
        for (int o = 16; o; o >>= 1)
            acc[c] += __shfl_xor_sync(0xffffffffu, acc[c], o);
    if (lane == 0) {
        float s0 = 0.f, s1 = 0.f;
        #pragma unroll
        for (int c = 0; c < C_OUT; c++) {
            g_h3[(size_t)node * C_OUT + c] = acc[c];
            s0 = fmaf(acc[c], As3[c], s0);
            s1 = fmaf(acc[c], Ad3[c], s1);
        }
        g_as[node] = s0;
        g_ad[node] = s1;
    }
}

// ---------------- layer 3 fused softmax + aggregation (C=10), warp per node ----------------
__global__ __launch_bounds__(256) void gat_agg3_csr(float* __restrict__ out,
                                                    const float* __restrict__ b3)
{
    int node = blockIdx.x * 8 + (threadIdx.x >> 5);
    int lane = threadIdx.x & 31;
    if (node >= N_NODES) return;

    const int start = g_rowstart[node];
    const int end   = g_rowstart[node + 1];
    const float adn = g_ad[node];
    const unsigned FULL = 0xffffffffu;

    float v[CAP];
    int   sv[CAP];
    float m = -INFINITY;
    int   cnt = 0;
    for (int i = start + lane; i < end; i += 32) {
        int s = g_esrc[i];
        float sc = leaky(g_as[s] + adn);
        if (cnt < CAP) { v[cnt] = sc; sv[cnt] = s; }
        cnt++;
        m = fmaxf(m, sc);
    }
    #pragma unroll
    for (int o = 16; o; o >>= 1) m = fmaxf(m, __shfl_xor_sync(FULL, m, o));

    float psum = 0.f;
    #pragma unroll
    for (int k = 0; k < CAP; k++) {
        if (k < cnt) { v[k] = __expf(v[k] - m); psum += v[k]; }
    }
    for (int i = start + lane + CAP * 32; i < end; i += 32) {
        int s = g_esrc[i];
        psum += __expf(leaky(g_as[s] + adn) - m);
    }
    #pragma unroll
    for (int o = 16; o; o >>= 1) psum += __shfl_xor_sync(FULL, psum, o);
    const float inv = 1.f / psum;

    float acc = 0.f;
    #pragma unroll
    for (int slot = 0; slot < CAP; slot++) {
        int base = start + slot * 32;
        if (base >= end) break;
        int nown = min(32, end - base);
        float vv = v[slot];
        int   ss = sv[slot];
        for (int owner = 0; owner < nown; owner++) {
            float c = __shfl_sync(FULL, vv, owner) * inv;
            int   s = __shfl_sync(FULL, ss, owner);
            if (lane < C_OUT) acc = fmaf(c, g_h3[(size_t)s * C_OUT + lane], acc);
        }
    }
    for (int i = start + CAP * 32; i < end; i++) {
        int s = g_esrc[i];
        float c = __expf(leaky(g_as[s] + adn) - m) * inv;
        if (lane < C_OUT) acc = fmaf(c, g_h3[(size_t)s * C_OUT + lane], acc);
    }

    if (lane < C_OUT) out[(size_t)node * C_OUT + lane] = acc + b3[lane];
}

// ---------------- host launcher (pure kernel launches; capture-safe) ----------------
extern "C" void kernel_launch(void* const* d_in, const int* in_sizes, int n_in,
                              void* d_out, int out_size)
{
    const float* x  = (const float*)d_in[0];
    const void*  ei = d_in[1];                    // int32 or int64, device-detected

    const float* W1  = (const float*)d_in[2];
    const float* as1 = (const float*)d_in[3];
    const float* ad1 = (const float*)d_in[4];
    const float* b1  = (const float*)d_in[5];
    const float* W2  = (const float*)d_in[6];
    const float* as2 = (const float*)d_in[7];
    const float* ad2 = (const float*)d_in[8];
    const float* b2  = (const float*)d_in[9];
    const float* W3  = (const float*)d_in[10];
    const float* as3 = (const float*)d_in[11];
    const float* ad3 = (const float*)d_in[12];
    const float* b3  = (const float*)d_in[13];
    float* out = (float*)d_out;

    const dim3 gemmGrid((N_NODES + 127) / 128, 2);
    const int  warpNodeBlocks = (N_NODES + 7) / 8;   // 8 warps/block
    const int  edgeBlocks     = (E_TOT + 255) / 256;
    const int  segBlk         = (N_NODES + 255) / 256;

    // ---- CSR build (once per launch) ----
    detect_dtype_kernel<<<1, 32>>>((const int*)ei);
    zero_cnt_kernel<<<segBlk, 256>>>();
    decode_hist_kernel<<<edgeBlocks, 256>>>(ei);
    scan1_kernel<<<SCAN_B, 256>>>();
    scan2_kernel<<<1, 256>>>();
    scan3_kernel<<<segBlk, 256>>>();
    scatter_kernel<<<edgeBlocks, 256>>>();

    // ---- layer 1: h -> buf0, agg -> buf1 ----
    sgemm256<<<gemmGrid, 256>>>(x, -1, W1, /*csel=*/0, N_NODES, /*reluA=*/0);
    alpha_kernel<<<warpNodeBlocks, 256>>>(0, as1, ad1);
    gat_agg_csr<<<warpNodeBlocks, 256>>>(/*hsel=*/0, /*osel=*/1, b1);

    // ---- layer 2: h -> buf0 (relu on A), agg -> buf2 ----
    sgemm256<<<gemmGrid, 256>>>(nullptr, 1, W2, /*csel=*/0, N_NODES, /*reluA=*/1);
    alpha_kernel<<<warpNodeBlocks, 256>>>(0, as2, ad2);
    gat_agg_csr<<<warpNodeBlocks, 256>>>(/*hsel=*/0, /*osel=*/2, b2);

    // ---- layer 3: h3 from relu(buf2), agg -> d_out ----
    gemm3_alpha_kernel<<<warpNodeBlocks, 256>>>(2, W3, as3, ad3);
    gat_agg3_csr<<<warpNodeBlocks, 256>>>(out, b3);
}

// round 16
// speedup vs baseline: 1.8674x; 1.0528x over previous
#include <cuda_runtime.h>
#include <math.h>
#include <stdint.h>

#define N_NODES 50000
#define N_EDGES 800000
#define E_TOT   (N_EDGES + N_NODES)   // 850000 (self loops appended)
#define D 256
#define C_OUT 10
#define NEG_SLOPE 0.2f
#define CAP 4                          // score slots per lane -> 128 edges/node fast path
#define SCAN_B ((N_NODES + 255) / 256) // 196 blocks for hierarchical scan

// ---------------- device scratch (no allocations allowed) ----------------
__device__ __align__(16) float g_buf0[(size_t)N_NODES * D];   // transformed feats h
__device__ __align__(16) float g_buf1[(size_t)N_NODES * D];   // layer-1 out / layer-2 in
__device__ __align__(16) float g_buf2[(size_t)N_NODES * D];   // layer-2 out / layer-3 in
__device__ __align__(16) float g_h3[(size_t)N_NODES * C_OUT]; // layer-3 transformed feats
__device__ float g_as[N_NODES];
__device__ float g_ad[N_NODES];
__device__ int   g_src[E_TOT];
__device__ int   g_dst[E_TOT];
__device__ int   g_cnt[N_NODES];
__device__ int   g_rowstart[N_NODES + 1];
__device__ int   g_cursor[N_NODES];
__device__ int   g_esrc[E_TOT];       // src ids grouped by dst (CSR)
__device__ int   g_bsum[SCAN_B];
__device__ int   g_boff[SCAN_B];
__device__ int   g_is64;

__device__ __forceinline__ float* getbuf(int k) {
    return (k == 0) ? g_buf0 : (k == 1) ? g_buf1 : g_buf2;
}

__device__ __forceinline__ float leaky(float v) {
    return v > 0.f ? v : NEG_SLOPE * v;
}

// ---------------- tf32 helpers ----------------
__device__ __forceinline__ unsigned f2tf32(float x) {
    unsigned r;
    asm("cvt.rna.tf32.f32 %0, %1;" : "=r"(r) : "f"(x));
    return r;
}

// m16n8k8 tf32 mma, row.col, fp32 accumulate (in place)
__device__ __forceinline__ void mma_tf32(float* c, const unsigned* a, const unsigned* b) {
    asm volatile(
        "mma.sync.aligned.m16n8k8.row.col.f32.tf32.tf32.f32 "
        "{%0,%1,%2,%3}, {%4,%5,%6,%7}, {%8,%9}, {%0,%1,%2,%3};"
        : "+f"(c[0]), "+f"(c[1]), "+f"(c[2]), "+f"(c[3])
        : "r"(a[0]), "r"(a[1]), "r"(a[2]), "r"(a[3]), "r"(b[0]), "r"(b[1]));
}

// ---------------- edge decode + CSR build ----------------
__global__ void detect_dtype_kernel(const int* __restrict__ ei32)
{
    int lane = threadIdx.x;                 // 32 threads
    int v = ei32[2 * lane + 1];             // odd words: all zero iff int64 data
    unsigned ballot = __ballot_sync(0xffffffffu, v != 0);
    if (lane == 0) g_is64 = (ballot == 0u) ? 1 : 0;
}

__global__ void zero_cnt_kernel()
{
    int i = blockIdx.x * blockDim.x + threadIdx.x;
    if (i < N_NODES) g_cnt[i] = 0;
}

__global__ void zero_alpha_kernel()
{
    int i = blockIdx.x * blockDim.x + threadIdx.x;
    if (i < N_NODES) { g_as[i] = 0.f; g_ad[i] = 0.f; }
}

__global__ void decode_hist_kernel(const void* __restrict__ ei_raw)
{
    int e = blockIdx.x * blockDim.x + threadIdx.x;
    if (e >= E_TOT) return;
    int s, d;
    if (e < N_EDGES) {
        if (g_is64) {
            const long long* p = (const long long*)ei_raw;
            s = (int)p[e];
            d = (int)p[N_EDGES + e];
        } else {
            const int* p = (const int*)ei_raw;
            s = p[e];
            d = p[N_EDGES + e];
        }
    } else {
        s = d = e - N_EDGES;               // self loop
    }
    g_src[e] = s;
    g_dst[e] = d;
    atomicAdd(&g_cnt[d], 1);
}

// ---- hierarchical exclusive scan of g_cnt -> g_rowstart / g_cursor ----
__global__ void scan1_kernel()           // per-block exclusive scan + block sums
{
    __shared__ int sh[256];
    int tid = threadIdx.x;
    int i = blockIdx.x * 256 + tid;
    int v = (i < N_NODES) ? g_cnt[i] : 0;
    sh[tid] = v;
    __syncthreads();
    #pragma unroll
    for (int off = 1; off < 256; off <<= 1) {
        int t = (tid >= off) ? sh[tid - off] : 0;
        __syncthreads();
        sh[tid] += t;
        __syncthreads();
    }
    if (i < N_NODES) g_rowstart[i] = sh[tid] - v;     // exclusive within block
    if (tid == 255) g_bsum[blockIdx.x] = sh[255];
}

__global__ void scan2_kernel()           // 1 block: exclusive scan of 196 block sums
{
    __shared__ int sh[256];
    int tid = threadIdx.x;
    int v = (tid < SCAN_B) ? g_bsum[tid] : 0;
    sh[tid] = v;
    __syncthreads();
    #pragma unroll
    for (int off = 1; off < 256; off <<= 1) {
        int t = (tid >= off) ? sh[tid - off] : 0;
        __syncthreads();
        sh[tid] += t;
        __syncthreads();
    }
    if (tid < SCAN_B) g_boff[tid] = sh[tid] - v;
    if (tid == 0) g_rowstart[N_NODES] = E_TOT;
}

__global__ void scan3_kernel()           // add block offsets, seed cursors
{
    int i = blockIdx.x * blockDim.x + threadIdx.x;
    if (i >= N_NODES) return;
    int r = g_rowstart[i] + g_boff[i >> 8];
    g_rowstart[i] = r;
    g_cursor[i]   = r;
}

__global__ void scatter_kernel()
{
    int e = blockIdx.x * blockDim.x + threadIdx.x;
    if (e >= E_TOT) return;
    int d = g_dst[e];
    int pos = atomicAdd(&g_cursor[d], 1);
    g_esrc[pos] = g_src[e];
}

// ---------------- TF32 tensor-core SGEMM + fused alpha epilogue --------------
// C[M,256] = A[M,256]*B[256,256]; also g_as[row] += C_row . a_src (atomic), same for a_dst.
// 128x128 block, BK=8 double-buffered, 8 warps (4 row x 2 col), warp tile 32x64.
// 3xTF32 split (hi*hi + hi*lo + lo*hi) -> ~fp32 accuracy.
#define GA_S 12     // A smem row stride (u32): bank = 12g+q mod 32 all-distinct
#define GB_S 136    // B smem k-row stride (u32): bank = 8q+g  mod 32 all-distinct

__global__ __launch_bounds__(256, 2) void sgemm256(const float* __restrict__ Aext,
                                                   int asel,
                                                   const float* __restrict__ B,
                                                   int csel, int M, int reluA,
                                                   const float* __restrict__ a_src,
                                                   const float* __restrict__ a_dst)
{
    const float* A = (asel < 0) ? Aext : getbuf(asel);
    float* C = getbuf(csel);

    __shared__ unsigned Ahi[2][128 * GA_S];
    __shared__ unsigned Alo[2][128 * GA_S];
    __shared__ unsigned Bhi[2][8 * GB_S];
    __shared__ unsigned Blo[2][8 * GB_S];

    const int tid  = threadIdx.x;
    const int lane = tid & 31;
    const int wid  = tid >> 5;
    const int wr = wid & 3;            // warp row -> m offset 32*wr
    const int wc = wid >> 2;           // warp col -> n offset 64*wc
    const int g  = lane >> 2;          // octet row 0..7
    const int q  = lane & 3;           // thread-in-group 0..3

    const int blockRow = blockIdx.x * 128;
    const int blockCol = blockIdx.y * 128;

    // global tile load assignment (per thread: 1 float4 of A, 1 float4 of B)
    const int arow = tid >> 1;          // 0..127
    const int ac4  = (tid & 1) * 4;     // 0 or 4
    const int brow = tid >> 5;          // 0..7
    const int bc4  = (tid & 31) * 4;    // 0..124
    const int gr   = blockRow + arow;

    float acc[2][8][4];
    #pragma unroll
    for (int mt = 0; mt < 2; mt++)
        #pragma unroll
        for (int nt = 0; nt < 8; nt++)
            #pragma unroll
            for (int r = 0; r < 4; r++) acc[mt][nt][r] = 0.f;

    const float4 zero4 = make_float4(0.f, 0.f, 0.f, 0.f);
    float4 pa, pb;

    // prologue: tile 0 -> regs -> smem[0]
    pa = (gr < M) ? *(const float4*)(A + (size_t)gr * 256 + ac4) : zero4;
    pb = *(const float4*)(B + (size_t)brow * 256 + blockCol + bc4);

    {
        float av[4] = { pa.x, pa.y, pa.z, pa.w };
        if (reluA) {
            #pragma unroll
            for (int j = 0; j < 4; j++) av[j] = fmaxf(av[j], 0.f);
        }
        int ai = arow * GA_S + ac4;
        #pragma unroll
        for (int j = 0; j < 4; j++) {
            unsigned hi = f2tf32(av[j]);
            Ahi[0][ai + j] = hi;
            Alo[0][ai + j] = f2tf32(av[j] - __uint_as_float(hi));
        }
        float bv[4] = { pb.x, pb.y, pb.z, pb.w };
        int bi = brow * GB_S + bc4;
        #pragma unroll
        for (int j = 0; j < 4; j++) {
            unsigned hi = f2tf32(bv[j]);
            Bhi[0][bi + j] = hi;
            Blo[0][bi + j] = f2tf32(bv[j] - __uint_as_float(hi));
        }
    }
    __syncthreads();

    int buf = 0;
    for (int kb = 0; kb < 32; kb++) {
        // prefetch next k-panel into regs
        if (kb < 31) {
            pa = (gr < M)
                ? *(const float4*)(A + (size_t)gr * 256 + (kb + 1) * 8 + ac4) : zero4;
            pb = *(const float4*)(B + (size_t)((kb + 1) * 8 + brow) * 256
                                  + blockCol + bc4);
        }

        // compute one k8 step from smem[buf]
        {
            unsigned ah[2][4], al[2][4];
            #pragma unroll
            for (int mt = 0; mt < 2; mt++) {
                int r0 = (wr * 32 + mt * 16 + g) * GA_S;
                int r1 = r0 + 8 * GA_S;
                ah[mt][0] = Ahi[buf][r0 + q];     al[mt][0] = Alo[buf][r0 + q];
                ah[mt][1] = Ahi[buf][r1 + q];     al[mt][1] = Alo[buf][r1 + q];
                ah[mt][2] = Ahi[buf][r0 + q + 4]; al[mt][2] = Alo[buf][r0 + q + 4];
                ah[mt][3] = Ahi[buf][r1 + q + 4]; al[mt][3] = Alo[buf][r1 + q + 4];
            }
            #pragma unroll
            for (int nt = 0; nt < 8; nt++) {
                int n = wc * 64 + nt * 8 + g;
                unsigned bh[2], bl[2];
                bh[0] = Bhi[buf][q * GB_S + n];
                bh[1] = Bhi[buf][(q + 4) * GB_S + n];
                bl[0] = Blo[buf][q * GB_S + n];
                bl[1] = Blo[buf][(q + 4) * GB_S + n];
                mma_tf32(acc[0][nt], al[0], bh);
                mma_tf32(acc[1][nt], al[1], bh);
                mma_tf32(acc[0][nt], ah[0], bl);
                mma_tf32(acc[1][nt], ah[1], bl);
                mma_tf32(acc[0][nt], ah[0], bh);
                mma_tf32(acc[1][nt], ah[1], bh);
            }
        }

        // split + store prefetched panel into the other buffer
        if (kb < 31) {
            float av[4] = { pa.x, pa.y, pa.z, pa.w };
            if (reluA) {
                #pragma unroll
                for (int j = 0; j < 4; j++) av[j] = fmaxf(av[j], 0.f);
            }
            int nb = buf ^ 1;
            int ai = arow * GA_S + ac4;
            #pragma unroll
            for (int j = 0; j < 4; j++) {
                unsigned hi = f2tf32(av[j]);
                Ahi[nb][ai + j] = hi;
                Alo[nb][ai + j] = f2tf32(av[j] - __uint_as_float(hi));
            }
            float bv[4] = { pb.x, pb.y, pb.z, pb.w };
            int bi = brow * GB_S + bc4;
            #pragma unroll
            for (int j = 0; j < 4; j++) {
                unsigned hi = f2tf32(bv[j]);
                Bhi[nb][bi + j] = hi;
                Blo[nb][bi + j] = f2tf32(bv[j] - __uint_as_float(hi));
            }
            __syncthreads();
        }
        buf ^= 1;
    }

    // ---- epilogue: store C + fused alpha (row-dot with a_src/a_dst) ----
    #pragma unroll
    for (int mt = 0; mt < 2; mt++) {
        int row0 = blockRow + wr * 32 + mt * 16 + g;
        int row1 = row0 + 8;
        float s0 = 0.f, d0 = 0.f, s1 = 0.f, d1 = 0.f;
        #pragma unroll
        for (int nt = 0; nt < 8; nt++) {
            int col = blockCol + wc * 64 + nt * 8 + q * 2;
            float asx = __ldg(a_src + col), asy = __ldg(a_src + col + 1);
            float adx = __ldg(a_dst + col), ady = __ldg(a_dst + col + 1);
            s0 = fmaf(acc[mt][nt][0], asx, fmaf(acc[mt][nt][1], asy, s0));
            d0 = fmaf(acc[mt][nt][0], adx, fmaf(acc[mt][nt][1], ady, d0));
            s1 = fmaf(acc[mt][nt][2], asx, fmaf(acc[mt][nt][3], asy, s1));
            d1 = fmaf(acc[mt][nt][2], adx, fmaf(acc[mt][nt][3], ady, d1));
            if (row0 < M)
                *(float2*)(C + (size_t)row0 * 256 + col) =
                    make_float2(acc[mt][nt][0], acc[mt][nt][1]);
            if (row1 < M)
                *(float2*)(C + (size_t)row1 * 256 + col) =
                    make_float2(acc[mt][nt][2], acc[mt][nt][3]);
        }
        // reduce across the 4 q-lanes of this octet row
        const unsigned FULL = 0xffffffffu;
        s0 += __shfl_xor_sync(FULL, s0, 1); s0 += __shfl_xor_sync(FULL, s0, 2);
        d0 += __shfl_xor_sync(FULL, d0, 1); d0 += __shfl_xor_sync(FULL, d0, 2);
        s1 += __shfl_xor_sync(FULL, s1, 1); s1 += __shfl_xor_sync(FULL, s1, 2);
        d1 += __shfl_xor_sync(FULL, d1, 1); d1 += __shfl_xor_sync(FULL, d1, 2);
        if (q == 0) {
            if (row0 < M) { atomicAdd(&g_as[row0], s0); atomicAdd(&g_ad[row0], d0); }
            if (row1 < M) { atomicAdd(&g_as[row1], s1); atomicAdd(&g_ad[row1], d1); }
        }
    }
}

// ---------------- fused softmax + aggregation, warp per dst node (D=256) ----------------
__global__ __launch_bounds__(256) void gat_agg_csr(int hsel, int osel,
                                                   const float* __restrict__ bias)
{
    const float* H = getbuf(hsel);
    float* out = getbuf(osel);

    int node = blockIdx.x * 8 + (threadIdx.x >> 5);
    int lane = threadIdx.x & 31;
    if (node >= N_NODES) return;

    const int start = g_rowstart[node];
    const int end   = g_rowstart[node + 1];
    const float adn = g_ad[node];
    const unsigned FULL = 0xffffffffu;

    float v[CAP];
    int   sv[CAP];
    float m = -INFINITY;
    int   cnt = 0;
    for (int i = start + lane; i < end; i += 32) {
        int s = g_esrc[i];
        float sc = leaky(g_as[s] + adn);
        if (cnt < CAP) { v[cnt] = sc; sv[cnt] = s; }
        cnt++;
        m = fmaxf(m, sc);
    }
    #pragma unroll
    for (int o = 16; o; o >>= 1) m = fmaxf(m, __shfl_xor_sync(FULL, m, o));

    float psum = 0.f;
    #pragma unroll
    for (int k = 0; k < CAP; k++) {
        if (k < cnt) { v[k] = __expf(v[k] - m); psum += v[k]; }
    }
    for (int i = start + lane + CAP * 32; i < end; i += 32) {     // rare tail
        int s = g_esrc[i];
        psum += __expf(leaky(g_as[s] + adn) - m);
    }
    #pragma unroll
    for (int o = 16; o; o >>= 1) psum += __shfl_xor_sync(FULL, psum, o);
    const float inv = 1.f / psum;

    float4 a0 = make_float4(0.f, 0.f, 0.f, 0.f);
    float4 a1 = make_float4(0.f, 0.f, 0.f, 0.f);
    #pragma unroll
    for (int slot = 0; slot < CAP; slot++) {
        int base = start + slot * 32;
        if (base >= end) break;
        int nown = min(32, end - base);
        float vv = v[slot];
        int   ss = sv[slot];
        for (int owner = 0; owner < nown; owner++) {
            float c = __shfl_sync(FULL, vv, owner) * inv;
            int   s = __shfl_sync(FULL, ss, owner);
            const float4* hr = (const float4*)(H + (size_t)s * D);
            float4 h0 = hr[lane];
            float4 h1 = hr[lane + 32];
            a0.x = fmaf(c, h0.x, a0.x); a0.y = fmaf(c, h0.y, a0.y);
            a0.z = fmaf(c, h0.z, a0.z); a0.w = fmaf(c, h0.w, a0.w);
            a1.x = fmaf(c, h1.x, a1.x); a1.y = fmaf(c, h1.y, a1.y);
            a1.z = fmaf(c, h1.z, a1.z); a1.w = fmaf(c, h1.w, a1.w);
        }
    }
    for (int i = start + CAP * 32; i < end; i++) {                // rare tail
        int s = g_esrc[i];
        float c = __expf(leaky(g_as[s] + adn) - m) * inv;
        const float4* hr = (const float4*)(H + (size_t)s * D);
        float4 h0 = hr[lane];
        float4 h1 = hr[lane + 32];
        a0.x = fmaf(c, h0.x, a0.x); a0.y = fmaf(c, h0.y, a0.y);
        a0.z = fmaf(c, h0.z, a0.z); a0.w = fmaf(c, h0.w, a0.w);
        a1.x = fmaf(c, h1.x, a1.x); a1.y = fmaf(c, h1.y, a1.y);
        a1.z = fmaf(c, h1.z, a1.z); a1.w = fmaf(c, h1.w, a1.w);
    }

    const float4 b0 = ((const float4*)bias)[lane];
    const float4 b1 = ((const float4*)bias)[lane + 32];
    a0.x += b0.x; a0.y += b0.y; a0.z += b0.z; a0.w += b0.w;
    a1.x += b1.x; a1.y += b1.y; a1.z += b1.z; a1.w += b1.w;
    float4* orow = (float4*)(out + (size_t)node * D);
    orow[lane]      = a0;
    orow[lane + 32] = a1;
}

// ---------------- layer 3: h3 = relu(H) @ W3 (256x10) + alpha dots ----------------
__global__ void gemm3_alpha_kernel(int hsel,
                                   const float* __restrict__ W3,
                                   const float* __restrict__ a_src,
                                   const float* __restrict__ a_dst)
{
    const float* H = getbuf(hsel);
    __shared__ float Ws[D * C_OUT];
    __shared__ float As3[C_OUT], Ad3[C_OUT];
    int tid = threadIdx.x;
    for (int i = tid; i < D * C_OUT; i += blockDim.x) Ws[i] = W3[i];
    if (tid < C_OUT) { As3[tid] = a_src[tid]; Ad3[tid] = a_dst[tid]; }
    __syncthreads();

    int node = blockIdx.x * 8 + (tid >> 5);
    int lane = tid & 31;
    if (node >= N_NODES) return;
    const float* row = H + (size_t)node * D;
    float acc[C_OUT];
    #pragma unroll
    for (int c = 0; c < C_OUT; c++) acc[c] = 0.f;
    #pragma unroll
    for (int k = lane; k < D; k += 32) {
        float h = fmaxf(row[k], 0.f);                  // fused relu
        #pragma unroll
        for (int c = 0; c < C_OUT; c++) acc[c] = fmaf(h, Ws[k * C_OUT + c], acc[c]);
    }
    #pragma unroll
    for (int c = 0; c < C_OUT; c++)
        #pragma unroll
        for (int o = 16; o; o >>= 1)
            acc[c] += __shfl_xor_sync(0xffffffffu, acc[c], o);
    if (lane == 0) {
        float s0 = 0.f, s1 = 0.f;
        #pragma unroll
        for (int c = 0; c < C_OUT; c++) {
            g_h3[(size_t)node * C_OUT + c] = acc[c];
            s0 = fmaf(acc[c], As3[c], s0);
            s1 = fmaf(acc[c], Ad3[c], s1);
        }
        g_as[node] = s0;
        g_ad[node] = s1;
    }
}

// ---------------- layer 3 fused softmax + aggregation (C=10), warp per node ----------------
__global__ __launch_bounds__(256) void gat_agg3_csr(float* __restrict__ out,
                                                    const float* __restrict__ b3)
{
    int node = blockIdx.x * 8 + (threadIdx.x >> 5);
    int lane = threadIdx.x & 31;
    if (node >= N_NODES) return;

    const int start = g_rowstart[node];
    const int end   = g_rowstart[node + 1];
    const float adn = g_ad[node];
    const unsigned FULL = 0xffffffffu;

    float v[CAP];
    int   sv[CAP];
    float m = -INFINITY;
    int   cnt = 0;
    for (int i = start + lane; i < end; i += 32) {
        int s = g_esrc[i];
        float sc = leaky(g_as[s] + adn);
        if (cnt < CAP) { v[cnt] = sc; sv[cnt] = s; }
        cnt++;
        m = fmaxf(m, sc);
    }
    #pragma unroll
    for (int o = 16; o; o >>= 1) m = fmaxf(m, __shfl_xor_sync(FULL, m, o));

    float psum = 0.f;
    #pragma unroll
    for (int k = 0; k < CAP; k++) {
        if (k < cnt) { v[k] = __expf(v[k] - m); psum += v[k]; }
    }
    for (int i = start + lane + CAP * 32; i < end; i += 32) {
        int s = g_esrc[i];
        psum += __expf(leaky(g_as[s] + adn) - m);
    }
    #pragma unroll
    for (int o = 16; o; o >>= 1) psum += __shfl_xor_sync(FULL, psum, o);
    const float inv = 1.f / psum;

    float acc = 0.f;
    #pragma unroll
    for (int slot = 0; slot < CAP; slot++) {
        int base = start + slot * 32;
        if (base >= end) break;
        int nown = min(32, end - base);
        float vv = v[slot];
        int   ss = sv[slot];
        for (int owner = 0; owner < nown; owner++) {
            float c = __shfl_sync(FULL, vv, owner) * inv;
            int   s = __shfl_sync(FULL, ss, owner);
            if (lane < C_OUT) acc = fmaf(c, g_h3[(size_t)s * C_OUT + lane], acc);
        }
    }
    for (int i = start + CAP * 32; i < end; i++) {
        int s = g_esrc[i];
        float c = __expf(leaky(g_as[s] + adn) - m) * inv;
        if (lane < C_OUT) acc = fmaf(c, g_h3[(size_t)s * C_OUT + lane], acc);
    }

    if (lane < C_OUT) out[(size_t)node * C_OUT + lane] = acc + b3[lane];
}

// ---------------- host launcher (pure kernel launches; capture-safe) ----------------
extern "C" void kernel_launch(void* const* d_in, const int* in_sizes, int n_in,
                              void* d_out, int out_size)
{
    const float* x  = (const float*)d_in[0];
    const void*  ei = d_in[1];                    // int32 or int64, device-detected

    const float* W1  = (const float*)d_in[2];
    const float* as1 = (const float*)d_in[3];
    const float* ad1 = (const float*)d_in[4];
    const float* b1  = (const float*)d_in[5];
    const float* W2  = (const float*)d_in[6];
    const float* as2 = (const float*)d_in[7];
    const float* ad2 = (const float*)d_in[8];
    const float* b2  = (const float*)d_in[9];
    const float* W3  = (const float*)d_in[10];
    const float* as3 = (const float*)d_in[11];
    const float* ad3 = (const float*)d_in[12];
    const float* b3  = (const float*)d_in[13];
    float* out = (float*)d_out;

    const dim3 gemmGrid((N_NODES + 127) / 128, 2);
    const int  warpNodeBlocks = (N_NODES + 7) / 8;   // 8 warps/block
    const int  edgeBlocks     = (E_TOT + 255) / 256;
    const int  segBlk         = (N_NODES + 255) / 256;

    // ---- CSR build (once per launch) ----
    detect_dtype_kernel<<<1, 32>>>((const int*)ei);
    zero_cnt_kernel<<<segBlk, 256>>>();
    decode_hist_kernel<<<edgeBlocks, 256>>>(ei);
    scan1_kernel<<<SCAN_B, 256>>>();
    scan2_kernel<<<1, 256>>>();
    scan3_kernel<<<segBlk, 256>>>();
    scatter_kernel<<<edgeBlocks, 256>>>();

    // ---- layer 1: h -> buf0 (alpha fused), agg -> buf1 ----
    zero_alpha_kernel<<<segBlk, 256>>>();
    sgemm256<<<gemmGrid, 256>>>(x, -1, W1, /*csel=*/0, N_NODES, /*reluA=*/0, as1, ad1);
    gat_agg_csr<<<warpNodeBlocks, 256>>>(/*hsel=*/0, /*osel=*/1, b1);

    // ---- layer 2: h -> buf0 (relu on A, alpha fused), agg -> buf2 ----
    zero_alpha_kernel<<<segBlk, 256>>>();
    sgemm256<<<gemmGrid, 256>>>(nullptr, 1, W2, /*csel=*/0, N_NODES, /*reluA=*/1, as2, ad2);
    gat_agg_csr<<<warpNodeBlocks, 256>>>(/*hsel=*/0, /*osel=*/2, b2);

    // ---- layer 3: h3 from relu(buf2), agg -> d_out ----
    gemm3_alpha_kernel<<<warpNodeBlocks, 256>>>(2, W3, as3, ad3);
    gat_agg3_csr<<<warpNodeBlocks, 256>>>(out, b3);
}